// round 6
// baseline (speedup 1.0000x reference)
#include <cuda_runtime.h>
#include <cuda_bf16.h>
#include <math.h>

// ---------------------------------------------------------------------------
// Problem constants: u (8,4096,1024) f32; D = 1024.
// Outputs (tuple order): y (8,4096,1024), gamma (8,4096,1), final (8,4096).
// ---------------------------------------------------------------------------
#define BB 8
#define TT 4096
#define DD 1024
#define ROWS (BB * TT)              // 32768
#define NN   (2 * DD)               // 2048  (V1 | V2 fused GEMM)
#define Y_ELEMS   (ROWS * DD)       // 33554432
#define G_ELEMS   (ROWS)            // 32768

// Scratch (device globals: allowed; no cudaMalloc anywhere)
__device__ float g_V[(size_t)ROWS * NN];     // 256 MiB: [row][0..1023]=V1, [1024..2047]=V2
__device__ float g_vecs[4 * DD];             // a1 | a2 | cB | cBf
__device__ float g_gamma[ROWS];

// ---------------------------------------------------------------------------
// f32x2 packed-FMA helpers (FFMA2: 2x fp32 FMA per instruction on sm_103a)
// ---------------------------------------------------------------------------
__device__ __forceinline__ unsigned long long ffma2(unsigned long long a,
                                                    unsigned long long b,
                                                    unsigned long long c) {
    unsigned long long d;
    asm("fma.rn.f32x2 %0, %1, %2, %3;" : "=l"(d) : "l"(a), "l"(b), "l"(c));
    return d;
}
__device__ __forceinline__ unsigned long long dup2(float x) {
    unsigned long long d;
    asm("mov.b64 %0, {%1, %1};" : "=l"(d) : "f"(x));
    return d;
}
__device__ __forceinline__ float2 unpk2(unsigned long long v) {
    float2 r;
    asm("mov.b64 {%0, %1}, %2;" : "=f"(r.x), "=f"(r.y) : "l"(v));
    return r;
}

// ---------------------------------------------------------------------------
// K0: precompute  a1 = w1@WB, a2 = w2@WBf, cB = Wc@WB, cBf = Wc@WBf
//     (a1[d] = sum_e w1[e] * WB[e,d], etc.)  Launch: <<<4,256>>>
// ---------------------------------------------------------------------------
__global__ void precompute_vectors_kernel(const float* __restrict__ WB,
                                          const float* __restrict__ WBf,
                                          const float* __restrict__ w1,
                                          const float* __restrict__ w2,
                                          const float* __restrict__ Wc) {
    int d = blockIdx.x * blockDim.x + threadIdx.x;   // 0..1023
    float a1 = 0.f, a2 = 0.f, cB = 0.f, cBf = 0.f;
    for (int e = 0; e < DD; ++e) {
        float wb = WB[e * DD + d];     // coalesced across d
        float wf = WBf[e * DD + d];
        float s1 = w1[e], s2 = w2[e], sc = Wc[e];
        a1  += s1 * wb;
        cB  += sc * wb;
        a2  += s2 * wf;
        cBf += sc * wf;
    }
    g_vecs[d]          = a1;
    g_vecs[DD + d]     = a2;
    g_vecs[2 * DD + d] = cB;
    g_vecs[3 * DD + d] = cBf;
}

// ---------------------------------------------------------------------------
// K1: gamma + final_output, one warp per row.
//   s1 = u[t] · (t==0 ? w1 : a1)
//   s2 = u2   · (t==T-1 ? w2 : a2)    with u2 = (t==T-1 ? u[t] : u[t+1])
//   gamma = sigmoid(s1 + s2 + b)
//   cf = u[t] · (t==0 ? Wc : cB);  cb = u2 · (t==T-1 ? Wc : cBf);  cu = u[t]·Wc
//   final = sigmoid(gamma*(cf+cb) + (1-gamma)*cu)
// Launch: <<<4096, 256>>>
// ---------------------------------------------------------------------------
__global__ void gamma_final_kernel(const float* __restrict__ u,
                                   const float* __restrict__ w1,
                                   const float* __restrict__ w2,
                                   const float* __restrict__ bias,
                                   const float* __restrict__ Wc,
                                   float* __restrict__ gamma_out,
                                   float* __restrict__ final_out) {
    int row  = blockIdx.x * 8 + (threadIdx.x >> 5);
    int lane = threadIdx.x & 31;
    int t = row & (TT - 1);

    const float* u1 = u + (size_t)row * DD;
    const float* u2 = (t == TT - 1) ? u1 : u1 + DD;
    const float* vS1 = (t == 0)      ? w1 : (g_vecs + 0);
    const float* vCf = (t == 0)      ? Wc : (g_vecs + 2 * DD);
    const float* vS2 = (t == TT - 1) ? w2 : (g_vecs + DD);
    const float* vCb = (t == TT - 1) ? Wc : (g_vecs + 3 * DD);

    float s1 = 0.f, s2 = 0.f, cf = 0.f, cb = 0.f, cu = 0.f;
#pragma unroll
    for (int it = 0; it < 8; ++it) {
        int i = lane * 4 + it * 128;
        float4 uu = *(const float4*)(u1 + i);
        float4 vv = *(const float4*)(u2 + i);
        float4 x1 = *(const float4*)(vS1 + i);
        float4 xc = *(const float4*)(vCf + i);
        float4 wc = *(const float4*)(Wc + i);
        float4 x2 = *(const float4*)(vS2 + i);
        float4 xb = *(const float4*)(vCb + i);
        s1 += uu.x * x1.x + uu.y * x1.y + uu.z * x1.z + uu.w * x1.w;
        cf += uu.x * xc.x + uu.y * xc.y + uu.z * xc.z + uu.w * xc.w;
        cu += uu.x * wc.x + uu.y * wc.y + uu.z * wc.z + uu.w * wc.w;
        s2 += vv.x * x2.x + vv.y * x2.y + vv.z * x2.z + vv.w * x2.w;
        cb += vv.x * xb.x + vv.y * xb.y + vv.z * xb.z + vv.w * xb.w;
    }
#pragma unroll
    for (int off = 16; off > 0; off >>= 1) {
        s1 += __shfl_down_sync(0xffffffffu, s1, off);
        s2 += __shfl_down_sync(0xffffffffu, s2, off);
        cf += __shfl_down_sync(0xffffffffu, cf, off);
        cb += __shfl_down_sync(0xffffffffu, cb, off);
        cu += __shfl_down_sync(0xffffffffu, cu, off);
    }
    if (lane == 0) {
        float g   = 1.f / (1.f + expf(-(s1 + s2 + bias[0])));
        float fin = 1.f / (1.f + expf(-(g * (cf + cb) + (1.f - g) * cu)));
        g_gamma[row]   = g;
        gamma_out[row] = g;
        final_out[row] = fin;
    }
}

// ---------------------------------------------------------------------------
// K2: fused NT GEMM.  C[m, n] = sum_k u[m,k] * W[n,k]
//     W = WB for n<1024 (V1), WBf for n>=1024 (V2). Output -> g_V.
// Tiles: 128x128x8, 256 threads, 8x8 per thread, double-buffered SMEM,
// FFMA2 (fma.rn.f32x2) inner product: B pairs loaded packed from SMEM,
// A broadcast-duplicated once per 4 FFMA2.
// Launch: grid (16, 256) = (N tiles, M tiles); N fastest for A L2 reuse.
// ---------------------------------------------------------------------------
#define SPAD 132   // padded SMEM row (avoids STS bank conflicts; keeps 16B align)

__global__ __launch_bounds__(256)
void gemm_kernel(const float* __restrict__ A,
                 const float* __restrict__ WB,
                 const float* __restrict__ WBf) {
    __shared__ __align__(16) float As[2][8][SPAD];
    __shared__ __align__(16) float Bs[2][8][SPAD];

    const int tid = threadIdx.x;
    const int tx = tid & 15;        // n quadrant (0..15)
    const int ty = tid >> 4;        // m quadrant (0..15)
    const int bm = blockIdx.y * 128;
    const int bn = blockIdx.x * 128;

    const float* W = (bn < DD) ? WB : WBf;
    const int nb   = (bn < DD) ? bn : bn - DD;

    const int lr = tid >> 1;          // load row within tile (0..127)
    const int lc = (tid & 1) * 4;     // k offset within BK (0 or 4)
    const float* Ag = A + (size_t)(bm + lr) * DD + lc;
    const float* Bg = W + (size_t)(nb + lr) * DD + lc;

    unsigned long long c[8][4];
#pragma unroll
    for (int i = 0; i < 8; ++i)
#pragma unroll
        for (int j = 0; j < 4; ++j) c[i][j] = 0ull;   // packed {0.f,0.f}

    // prologue: load tile 0
    float4 a_ld = *(const float4*)(Ag);
    float4 b_ld = *(const float4*)(Bg);
    As[0][lc + 0][lr] = a_ld.x;  As[0][lc + 1][lr] = a_ld.y;
    As[0][lc + 2][lr] = a_ld.z;  As[0][lc + 3][lr] = a_ld.w;
    Bs[0][lc + 0][lr] = b_ld.x;  Bs[0][lc + 1][lr] = b_ld.y;
    Bs[0][lc + 2][lr] = b_ld.z;  Bs[0][lc + 3][lr] = b_ld.w;
    __syncthreads();

    const int KT = DD / 8;   // 128 k-tiles
    for (int kt = 0; kt < KT; ++kt) {
        const int cur = kt & 1;
        if (kt < KT - 1) {
            a_ld = *(const float4*)(Ag + (kt + 1) * 8);
            b_ld = *(const float4*)(Bg + (kt + 1) * 8);
        }
#pragma unroll
        for (int k = 0; k < 8; ++k) {
            const float* as = &As[cur][k][0];
            const float* bs = &Bs[cur][k][0];
            float4 af0 = *(const float4*)(as + ty * 4);
            float4 af1 = *(const float4*)(as + 64 + ty * 4);
            ulonglong2 bq0 = *(const ulonglong2*)(bs + tx * 4);
            ulonglong2 bq1 = *(const ulonglong2*)(bs + 64 + tx * 4);
            unsigned long long ad[8];
            ad[0] = dup2(af0.x); ad[1] = dup2(af0.y);
            ad[2] = dup2(af0.z); ad[3] = dup2(af0.w);
            ad[4] = dup2(af1.x); ad[5] = dup2(af1.y);
            ad[6] = dup2(af1.z); ad[7] = dup2(af1.w);
#pragma unroll
            for (int i = 0; i < 8; ++i) {
                c[i][0] = ffma2(ad[i], bq0.x, c[i][0]);
                c[i][1] = ffma2(ad[i], bq0.y, c[i][1]);
                c[i][2] = ffma2(ad[i], bq1.x, c[i][2]);
                c[i][3] = ffma2(ad[i], bq1.y, c[i][3]);
            }
        }
        if (kt < KT - 1) {
            const int nxt = cur ^ 1;
            As[nxt][lc + 0][lr] = a_ld.x;  As[nxt][lc + 1][lr] = a_ld.y;
            As[nxt][lc + 2][lr] = a_ld.z;  As[nxt][lc + 3][lr] = a_ld.w;
            Bs[nxt][lc + 0][lr] = b_ld.x;  Bs[nxt][lc + 1][lr] = b_ld.y;
            Bs[nxt][lc + 2][lr] = b_ld.z;  Bs[nxt][lc + 3][lr] = b_ld.w;
        }
        __syncthreads();
    }

    // epilogue: write C to g_V
#pragma unroll
    for (int i = 0; i < 8; ++i) {
        int m = bm + ((i < 4) ? (ty * 4 + i) : (64 + ty * 4 + (i - 4)));
        float* out0 = g_V + (size_t)m * NN + bn + tx * 4;
        float2 p0 = unpk2(c[i][0]), p1 = unpk2(c[i][1]);
        float2 p2 = unpk2(c[i][2]), p3 = unpk2(c[i][3]);
        *(float4*)out0        = make_float4(p0.x, p0.y, p1.x, p1.y);
        *(float4*)(out0 + 64) = make_float4(p2.x, p2.y, p3.x, p3.y);
    }
}

// ---------------------------------------------------------------------------
// K3: y epilogue. One block per row (256 threads x float4 = 1024 elems).
//   xf = (t==0)    ? u[r] : V1[r]
//   xb = (t==T-1)  ? u[r] : V2[r+1]
//   y  = g*(xf+xb) + (1-g)*u
// Launch: <<<32768, 256>>>
// ---------------------------------------------------------------------------
__global__ void y_epilogue_kernel(const float* __restrict__ u,
                                  float* __restrict__ y) {
    int r = blockIdx.x;
    int t = r & (TT - 1);
    int d = threadIdx.x * 4;
    float g = g_gamma[r];

    float4 uu = *(const float4*)(u + (size_t)r * DD + d);
    float4 xf = (t == 0) ? uu
              : *(const float4*)(g_V + (size_t)r * NN + d);
    float4 xb = (t == TT - 1) ? uu
              : *(const float4*)(g_V + (size_t)(r + 1) * NN + DD + d);
    float og = 1.f - g;
    float4 out;
    out.x = g * (xf.x + xb.x) + og * uu.x;
    out.y = g * (xf.y + xb.y) + og * uu.y;
    out.z = g * (xf.z + xb.z) + og * uu.z;
    out.w = g * (xf.w + xb.w) + og * uu.w;
    *(float4*)(y + (size_t)r * DD + d) = out;
}

// ---------------------------------------------------------------------------
// kernel_launch: inputs per metadata order:
//   0:u  1:WA(unused)  2:WB  3:WAf(unused)  4:WBf  5:w1  6:w2  7:b  8:Wc
// Output: [y | gamma | final] flattened f32.
// ---------------------------------------------------------------------------
extern "C" void kernel_launch(void* const* d_in, const int* in_sizes, int n_in,
                              void* d_out, int out_size) {
    (void)in_sizes; (void)n_in; (void)out_size;
    const float* u   = (const float*)d_in[0];
    const float* WB  = (const float*)d_in[2];
    const float* WBf = (const float*)d_in[4];
    const float* w1  = (const float*)d_in[5];
    const float* w2  = (const float*)d_in[6];
    const float* b   = (const float*)d_in[7];
    const float* Wc  = (const float*)d_in[8];

    float* y         = (float*)d_out;
    float* gamma_out = y + Y_ELEMS;
    float* final_out = gamma_out + G_ELEMS;

    precompute_vectors_kernel<<<DD / 256, 256>>>(WB, WBf, w1, w2, Wc);
    gamma_final_kernel<<<ROWS / 8, 256>>>(u, w1, w2, b, Wc, gamma_out, final_out);
    gemm_kernel<<<dim3(NN / 128, ROWS / 128), 256>>>(u, WB, WBf);
    y_epilogue_kernel<<<ROWS, 256>>>(u, y);
}

// round 8
// speedup vs baseline: 3.9440x; 3.9440x over previous
#include <cuda_runtime.h>
#include <cuda_fp16.h>
#include <math.h>
#include <stdint.h>

// ---------------------------------------------------------------------------
// Problem: u (8,4096,1024) f32. Outputs: y (8,4096,1024), gamma, final.
// Dominant cost: C[32768,2048] = u @ [WB;WBf]^T  -> fp16 mma.sync GEMM
// (tcgen05 unavailable: toolchain emits compute_103 PTX, not 103a).
// ---------------------------------------------------------------------------
#define BB 8
#define TT 4096
#define DD 1024
#define ROWS (BB * TT)              // 32768  (M)
#define NN   (2 * DD)               // 2048   (N)
#define KK   DD                     // 1024   (K)
#define Y_ELEMS   (ROWS * DD)
#define G_ELEMS   (ROWS)

// GEMM tiling
#define BM 128
#define BN 128
#define BK 64
#define STAGES 4
#define NCHUNK (KK / BK)            // 16
#define OFF_A 0
#define OFF_B (BM * BK * 2)         // 16384
#define STAGE_BYTES (2 * BM * BK * 2)   // 32768
#define SMEM_DYN (STAGES * STAGE_BYTES) // 131072

// Device-global scratch (no cudaMalloc anywhere)
__device__ float  g_V[(size_t)ROWS * NN];        // 256 MiB: V1 | V2 (fp32)
__device__ __half g_Af[(size_t)ROWS * KK];       // 64 MiB
__device__ __half g_Bf[(size_t)NN * KK];         // 4 MiB: rows 0..1023 = WB, 1024.. = WBf
__device__ float  g_vecs[4 * DD];                // a1 | a2 | cB | cBf
__device__ float  g_gamma[ROWS];

// ---------------------------------------------------------------------------
// PTX helpers (sm_80-class only: cp.async, ldmatrix, mma.sync)
// ---------------------------------------------------------------------------
__device__ __forceinline__ uint32_t smem_u32(const void* p) {
    uint32_t a;
    asm("{ .reg .u64 t; cvta.to.shared.u64 t, %1; cvt.u32.u64 %0, t; }"
        : "=r"(a) : "l"(p));
    return a;
}
__device__ __forceinline__ void cpasync16(uint32_t dst, const void* src) {
    asm volatile("cp.async.cg.shared.global [%0], [%1], 16;" :: "r"(dst), "l"(src));
}
#define CP_COMMIT() asm volatile("cp.async.commit_group;" ::: "memory")
#define CP_WAIT_2() asm volatile("cp.async.wait_group 2;" ::: "memory")
#define CP_WAIT_1() asm volatile("cp.async.wait_group 1;" ::: "memory")
#define CP_WAIT_0() asm volatile("cp.async.wait_group 0;" ::: "memory")

__device__ __forceinline__ void ldm_x4(uint32_t* r, uint32_t addr) {
    asm volatile("ldmatrix.sync.aligned.m8n8.x4.shared.b16 {%0,%1,%2,%3}, [%4];"
                 : "=r"(r[0]), "=r"(r[1]), "=r"(r[2]), "=r"(r[3]) : "r"(addr));
}
__device__ __forceinline__ void mma16816(float* c, const uint32_t* a,
                                         const uint32_t* b) {
    asm volatile("mma.sync.aligned.m16n8k16.row.col.f32.f16.f16.f32 "
                 "{%0,%1,%2,%3}, {%4,%5,%6,%7}, {%8,%9}, {%0,%1,%2,%3};"
                 : "+f"(c[0]), "+f"(c[1]), "+f"(c[2]), "+f"(c[3])
                 : "r"(a[0]), "r"(a[1]), "r"(a[2]), "r"(a[3]),
                   "r"(b[0]), "r"(b[1]));
}

// ---------------------------------------------------------------------------
// K0a: u -> fp16.  grid 32768 x 256, 4 elems/thread.
// ---------------------------------------------------------------------------
__global__ void convert_u_kernel(const float* __restrict__ u) {
    size_t i = ((size_t)blockIdx.x * 256 + threadIdx.x) * 4;
    float4 x = *(const float4*)(u + i);
    union { __half h[4]; uint2 v; } H;
    H.h[0] = __float2half_rn(x.x);  H.h[1] = __float2half_rn(x.y);
    H.h[2] = __float2half_rn(x.z);  H.h[3] = __float2half_rn(x.w);
    *(uint2*)(g_Af + i) = H.v;
}

// K0b: [WB;WBf] -> fp16.  grid 2048 x 256.
__global__ void convert_w_kernel(const float* __restrict__ WB,
                                 const float* __restrict__ WBf) {
    size_t i = ((size_t)blockIdx.x * 256 + threadIdx.x) * 4;
    const float* src = (i < (size_t)DD * DD) ? (WB + i) : (WBf + i - (size_t)DD * DD);
    float4 x = *(const float4*)src;
    union { __half h[4]; uint2 v; } H;
    H.h[0] = __float2half_rn(x.x);  H.h[1] = __float2half_rn(x.y);
    H.h[2] = __float2half_rn(x.z);  H.h[3] = __float2half_rn(x.w);
    *(uint2*)(g_Bf + i) = H.v;
}

// ---------------------------------------------------------------------------
// K1: precompute a1 = w1@WB, a2 = w2@WBf, cB = Wc@WB, cBf = Wc@WBf (fp32 exact)
// ---------------------------------------------------------------------------
__global__ void precompute_vectors_kernel(const float* __restrict__ WB,
                                          const float* __restrict__ WBf,
                                          const float* __restrict__ w1,
                                          const float* __restrict__ w2,
                                          const float* __restrict__ Wc) {
    int d = blockIdx.x * blockDim.x + threadIdx.x;
    float a1 = 0.f, a2 = 0.f, cB = 0.f, cBf = 0.f;
    for (int e = 0; e < DD; ++e) {
        float wb = WB[e * DD + d];
        float wf = WBf[e * DD + d];
        a1  += w1[e] * wb;
        cB  += Wc[e] * wb;
        a2  += w2[e] * wf;
        cBf += Wc[e] * wf;
    }
    g_vecs[d] = a1; g_vecs[DD + d] = a2;
    g_vecs[2 * DD + d] = cB; g_vecs[3 * DD + d] = cBf;
}

// ---------------------------------------------------------------------------
// K2: gamma + final (one warp per row, fp32 dot products — exact path)
// ---------------------------------------------------------------------------
__global__ void gamma_final_kernel(const float* __restrict__ u,
                                   const float* __restrict__ w1,
                                   const float* __restrict__ w2,
                                   const float* __restrict__ bias,
                                   const float* __restrict__ Wc,
                                   float* __restrict__ gamma_out,
                                   float* __restrict__ final_out) {
    int row  = blockIdx.x * 8 + (threadIdx.x >> 5);
    int lane = threadIdx.x & 31;
    int t = row & (TT - 1);

    const float* u1 = u + (size_t)row * DD;
    const float* u2 = (t == TT - 1) ? u1 : u1 + DD;
    const float* vS1 = (t == 0)      ? w1 : (g_vecs + 0);
    const float* vCf = (t == 0)      ? Wc : (g_vecs + 2 * DD);
    const float* vS2 = (t == TT - 1) ? w2 : (g_vecs + DD);
    const float* vCb = (t == TT - 1) ? Wc : (g_vecs + 3 * DD);

    float s1 = 0.f, s2 = 0.f, cf = 0.f, cb = 0.f, cu = 0.f;
#pragma unroll
    for (int it = 0; it < 8; ++it) {
        int i = lane * 4 + it * 128;
        float4 uu = *(const float4*)(u1 + i);
        float4 vv = *(const float4*)(u2 + i);
        float4 x1 = *(const float4*)(vS1 + i);
        float4 xc = *(const float4*)(vCf + i);
        float4 wc = *(const float4*)(Wc + i);
        float4 x2 = *(const float4*)(vS2 + i);
        float4 xb = *(const float4*)(vCb + i);
        s1 += uu.x * x1.x + uu.y * x1.y + uu.z * x1.z + uu.w * x1.w;
        cf += uu.x * xc.x + uu.y * xc.y + uu.z * xc.z + uu.w * xc.w;
        cu += uu.x * wc.x + uu.y * wc.y + uu.z * wc.z + uu.w * wc.w;
        s2 += vv.x * x2.x + vv.y * x2.y + vv.z * x2.z + vv.w * x2.w;
        cb += vv.x * xb.x + vv.y * xb.y + vv.z * xb.z + vv.w * xb.w;
    }
#pragma unroll
    for (int off = 16; off > 0; off >>= 1) {
        s1 += __shfl_down_sync(0xffffffffu, s1, off);
        s2 += __shfl_down_sync(0xffffffffu, s2, off);
        cf += __shfl_down_sync(0xffffffffu, cf, off);
        cb += __shfl_down_sync(0xffffffffu, cb, off);
        cu += __shfl_down_sync(0xffffffffu, cu, off);
    }
    if (lane == 0) {
        float g   = 1.f / (1.f + expf(-(s1 + s2 + bias[0])));
        float fin = 1.f / (1.f + expf(-(g * (cf + cb) + (1.f - g) * cu)));
        g_gamma[row]   = g;
        gamma_out[row] = g;
        final_out[row] = fin;
    }
}

// ---------------------------------------------------------------------------
// K3: fp16 mma.sync GEMM.  C = Af @ Bf^T (both K-major), fp32 accumulate.
// CTA 128x128x64, 4-stage cp.async, 256 thr, 8 warps (2m x 4n), warp 64x32.
// SMEM tiles: 128 rows x 128B, xor-swizzled 16B chunks (conflict-free ldmatrix).
// grid (NN/BN = 16, ROWS/BM = 256), x fastest for A-row L2 reuse.
// ---------------------------------------------------------------------------
__global__ __launch_bounds__(256, 1)
void gemm_hmma_kernel() {
    extern __shared__ __align__(128) char dsm[];
    const uint32_t sbase = smem_u32(dsm);

    const int tid  = threadIdx.x;
    const int wid  = tid >> 5;
    const int lane = tid & 31;
    const int bm = blockIdx.y * BM;
    const int bn = blockIdx.x * BN;
    const int wm = (wid >> 2) * 64;     // warp m offset within CTA tile
    const int wn = (wid & 3) * 32;      // warp n offset

    const __half* Ag0 = g_Af + (size_t)bm * KK;
    const __half* Bg0 = g_Bf + (size_t)bn * KK;

    // global->smem loader: 8 cp.async(16B)/thread/stage (A:4, B:4)
    const int lrow = tid >> 3;          // 0..31, +j*32
    const int lchk = tid & 7;           // 16B chunk within 128B row
    auto load_stage = [&](int kchunk, int slot) {
        uint32_t sb = sbase + slot * STAGE_BYTES;
        int kb = kchunk * BK;
#pragma unroll
        for (int j = 0; j < 4; ++j) {
            int r = lrow + j * 32;
            uint32_t sw = (uint32_t)((lchk ^ (r & 7)) << 4);
            uint32_t so = (uint32_t)(r * 128) + sw;
            const __half* ga = Ag0 + (size_t)r * KK + kb + lchk * 8;
            const __half* gb = Bg0 + (size_t)r * KK + kb + lchk * 8;
            cpasync16(sb + OFF_A + so, ga);
            cpasync16(sb + OFF_B + so, gb);
        }
    };

    // per-thread ldmatrix row bases (A: m16k16 x4; B: n16k16 x4 -> 2 n-tiles)
    uint32_t a_base[4], b_base[2];
    int a_rx[4], b_rx[2];
    const int a_ch = lane >> 4;                 // 0/1 -> k 0-7 / 8-15
    const int b_ch = (lane >> 3) & 1;
#pragma unroll
    for (int mi = 0; mi < 4; ++mi) {
        int r = wm + mi * 16 + (lane & 15);
        a_base[mi] = OFF_A + (uint32_t)(r * 128);
        a_rx[mi] = r & 7;
    }
#pragma unroll
    for (int p = 0; p < 2; ++p) {
        int r = wn + p * 16 + (lane & 7) + ((lane >> 4) << 3);
        b_base[p] = OFF_B + (uint32_t)(r * 128);
        b_rx[p] = r & 7;
    }

    float acc[4][4][4];
#pragma unroll
    for (int mi = 0; mi < 4; ++mi)
#pragma unroll
        for (int nj = 0; nj < 4; ++nj)
#pragma unroll
            for (int q = 0; q < 4; ++q) acc[mi][nj][q] = 0.f;

    // prologue: stages 0..2
    load_stage(0, 0); CP_COMMIT();
    load_stage(1, 1); CP_COMMIT();
    load_stage(2, 2); CP_COMMIT();

    for (int c = 0; c < NCHUNK; ++c) {
        if (c <= NCHUNK - 3)      CP_WAIT_2();
        else if (c == NCHUNK - 2) CP_WAIT_1();
        else                      CP_WAIT_0();
        __syncthreads();

        if (c + 3 < NCHUNK) { load_stage(c + 3, (c + 3) & (STAGES - 1)); CP_COMMIT(); }

        const uint32_t slot = sbase + (uint32_t)((c & (STAGES - 1)) * STAGE_BYTES);

        uint32_t af[2][16], bf[2][8];
        // fetch k-step 0
#pragma unroll
        for (int mi = 0; mi < 4; ++mi)
            ldm_x4(af[0] + mi * 4, slot + a_base[mi] + (uint32_t)(((a_ch) ^ a_rx[mi]) << 4));
#pragma unroll
        for (int p = 0; p < 2; ++p)
            ldm_x4(bf[0] + p * 4, slot + b_base[p] + (uint32_t)(((b_ch) ^ b_rx[p]) << 4));

#pragma unroll
        for (int ks = 0; ks < 4; ++ks) {
            if (ks < 3) {
                int kc = (ks + 1) * 2;
                uint32_t* an = af[(ks + 1) & 1];
                uint32_t* bn2 = bf[(ks + 1) & 1];
#pragma unroll
                for (int mi = 0; mi < 4; ++mi)
                    ldm_x4(an + mi * 4, slot + a_base[mi] + (uint32_t)(((kc + a_ch) ^ a_rx[mi]) << 4));
#pragma unroll
                for (int p = 0; p < 2; ++p)
                    ldm_x4(bn2 + p * 4, slot + b_base[p] + (uint32_t)(((kc + b_ch) ^ b_rx[p]) << 4));
            }
            const uint32_t* a = af[ks & 1];
            const uint32_t* b = bf[ks & 1];
#pragma unroll
            for (int mi = 0; mi < 4; ++mi)
#pragma unroll
                for (int nj = 0; nj < 4; ++nj)
                    mma16816(acc[mi][nj], a + mi * 4, b + nj * 2);
        }
        __syncthreads();
    }

    // epilogue: fp32 C -> g_V
    const int lr = lane >> 2;
    const int lc = (lane & 3) * 2;
    float* Cb = g_V + (size_t)(bm + wm) * NN + bn + wn;
#pragma unroll
    for (int mi = 0; mi < 4; ++mi) {
#pragma unroll
        for (int nj = 0; nj < 4; ++nj) {
            float* p0 = Cb + (size_t)(mi * 16 + lr) * NN + nj * 8 + lc;
            *(float2*)p0              = make_float2(acc[mi][nj][0], acc[mi][nj][1]);
            *(float2*)(p0 + 8 * NN)   = make_float2(acc[mi][nj][2], acc[mi][nj][3]);
        }
    }
}

// ---------------------------------------------------------------------------
// K4: y epilogue (DRAM-roofline): y = g*(xf+xb) + (1-g)*u
//   xf = (t==0) ? u[r] : V1[r];  xb = (t==T-1) ? u[r] : V2[r+1]
// ---------------------------------------------------------------------------
__global__ void y_epilogue_kernel(const float* __restrict__ u,
                                  float* __restrict__ y) {
    int r = blockIdx.x;
    int t = r & (TT - 1);
    int d = threadIdx.x * 4;
    float g = g_gamma[r];

    float4 uu = *(const float4*)(u + (size_t)r * DD + d);
    float4 xf = (t == 0) ? uu
              : *(const float4*)(g_V + (size_t)r * NN + d);
    float4 xb = (t == TT - 1) ? uu
              : *(const float4*)(g_V + (size_t)(r + 1) * NN + DD + d);
    float og = 1.f - g;
    float4 out;
    out.x = g * (xf.x + xb.x) + og * uu.x;
    out.y = g * (xf.y + xb.y) + og * uu.y;
    out.z = g * (xf.z + xb.z) + og * uu.z;
    out.w = g * (xf.w + xb.w) + og * uu.w;
    *(float4*)(y + (size_t)r * DD + d) = out;
}

// ---------------------------------------------------------------------------
// kernel_launch: inputs 0:u 1:WA(dead) 2:WB 3:WAf(dead) 4:WBf 5:w1 6:w2 7:b 8:Wc
// Output: [y | gamma | final] flattened f32.
// ---------------------------------------------------------------------------
extern "C" void kernel_launch(void* const* d_in, const int* in_sizes, int n_in,
                              void* d_out, int out_size) {
    (void)in_sizes; (void)n_in; (void)out_size;
    const float* u   = (const float*)d_in[0];
    const float* WB  = (const float*)d_in[2];
    const float* WBf = (const float*)d_in[4];
    const float* w1  = (const float*)d_in[5];
    const float* w2  = (const float*)d_in[6];
    const float* b   = (const float*)d_in[7];
    const float* Wc  = (const float*)d_in[8];

    float* y         = (float*)d_out;
    float* gamma_out = y + Y_ELEMS;
    float* final_out = gamma_out + G_ELEMS;

    cudaFuncSetAttribute(gemm_hmma_kernel,
                         cudaFuncAttributeMaxDynamicSharedMemorySize, SMEM_DYN);

    convert_u_kernel<<<Y_ELEMS / 1024, 256>>>(u);
    convert_w_kernel<<<(NN * KK) / 1024, 256>>>(WB, WBf);
    precompute_vectors_kernel<<<DD / 256, 256>>>(WB, WBf, w1, w2, Wc);
    gamma_final_kernel<<<ROWS / 8, 256>>>(u, w1, w2, b, Wc, gamma_out, final_out);
    gemm_hmma_kernel<<<dim3(NN / BN, ROWS / BM), 256, SMEM_DYN>>>();
    y_epilogue_kernel<<<ROWS, 256>>>(u, y);
}

// round 9
// speedup vs baseline: 4.3609x; 1.1057x over previous
#include <cuda_runtime.h>
#include <cuda_fp16.h>
#include <math.h>
#include <stdint.h>

// ---------------------------------------------------------------------------
// Problem: u (8,4096,1024) f32. Outputs: y (8,4096,1024), gamma, final.
// Fully fused: gamma kernel also emits u in fp16; GEMM computes
//   C1[m] = u[m] @ WB^T  (cols j..j+63)   and
//   C2[m] = u[m+1] @ WBf^T (cols j..j+63)
// and writes y = g*(xf+xb) + (1-g)*u directly (no V scratch in DRAM).
// ---------------------------------------------------------------------------
#define BB 8
#define TT 4096
#define DD 1024
#define ROWS (BB * TT)              // 32768  (M)
#define KK   DD                     // 1024   (K)
#define Y_ELEMS   (ROWS * DD)
#define G_ELEMS   (ROWS)

// GEMM tiling
#define BM 128
#define XN 64                        // V-columns per CTA (for each of C1, C2)
#define BK 64
#define STAGES 4
#define NCHUNK (KK / BK)             // 16
#define OFF_A0 0
#define OFF_A1 16384
#define OFF_B  32768
#define STAGE_BYTES 49152            // A0(16K) + A1(16K) + B(16K)
#define SMEM_DYN (STAGES * STAGE_BYTES)   // 196608
#define CS_STRIDE 68                 // fp32 staging stride (bank-friendly)

// Device-global scratch (no cudaMalloc anywhere)
__device__ __half g_Af[(size_t)ROWS * KK];       // 64 MiB  (u in fp16)
__device__ __half g_Bf[(size_t)2 * DD * KK];     // 4 MiB: rows 0..1023 WB, 1024.. WBf
__device__ float  g_vecs[4 * DD];                // a1 | a2 | cB | cBf
__device__ float  g_gamma[ROWS];

// ---------------------------------------------------------------------------
// PTX helpers (sm_80-class only: cp.async, ldmatrix, mma.sync)
// ---------------------------------------------------------------------------
__device__ __forceinline__ uint32_t smem_u32(const void* p) {
    uint32_t a;
    asm("{ .reg .u64 t; cvta.to.shared.u64 t, %1; cvt.u32.u64 %0, t; }"
        : "=r"(a) : "l"(p));
    return a;
}
__device__ __forceinline__ void cpasync16(uint32_t dst, const void* src) {
    asm volatile("cp.async.cg.shared.global [%0], [%1], 16;" :: "r"(dst), "l"(src));
}
#define CP_COMMIT() asm volatile("cp.async.commit_group;" ::: "memory")
#define CP_WAIT_2() asm volatile("cp.async.wait_group 2;" ::: "memory")
#define CP_WAIT_1() asm volatile("cp.async.wait_group 1;" ::: "memory")
#define CP_WAIT_0() asm volatile("cp.async.wait_group 0;" ::: "memory")

__device__ __forceinline__ void ldm_x4(uint32_t* r, uint32_t addr) {
    asm volatile("ldmatrix.sync.aligned.m8n8.x4.shared.b16 {%0,%1,%2,%3}, [%4];"
                 : "=r"(r[0]), "=r"(r[1]), "=r"(r[2]), "=r"(r[3]) : "r"(addr));
}
__device__ __forceinline__ void mma16816(float* c, const uint32_t* a,
                                         const uint32_t* b) {
    asm volatile("mma.sync.aligned.m16n8k16.row.col.f32.f16.f16.f32 "
                 "{%0,%1,%2,%3}, {%4,%5,%6,%7}, {%8,%9}, {%0,%1,%2,%3};"
                 : "+f"(c[0]), "+f"(c[1]), "+f"(c[2]), "+f"(c[3])
                 : "r"(a[0]), "r"(a[1]), "r"(a[2]), "r"(a[3]),
                   "r"(b[0]), "r"(b[1]));
}

// ---------------------------------------------------------------------------
// K0: [WB;WBf] -> fp16.  grid 2048 x 256.
// ---------------------------------------------------------------------------
__global__ void convert_w_kernel(const float* __restrict__ WB,
                                 const float* __restrict__ WBf) {
    size_t i = ((size_t)blockIdx.x * 256 + threadIdx.x) * 4;
    const float* src = (i < (size_t)DD * DD) ? (WB + i) : (WBf + i - (size_t)DD * DD);
    float4 x = *(const float4*)src;
    union { __half h[4]; uint2 v; } H;
    H.h[0] = __float2half_rn(x.x);  H.h[1] = __float2half_rn(x.y);
    H.h[2] = __float2half_rn(x.z);  H.h[3] = __float2half_rn(x.w);
    *(uint2*)(g_Bf + i) = H.v;
}

// ---------------------------------------------------------------------------
// K1: precompute a1 = w1@WB, a2 = w2@WBf, cB = Wc@WB, cBf = Wc@WBf (fp32 exact)
// ---------------------------------------------------------------------------
__global__ void precompute_vectors_kernel(const float* __restrict__ WB,
                                          const float* __restrict__ WBf,
                                          const float* __restrict__ w1,
                                          const float* __restrict__ w2,
                                          const float* __restrict__ Wc) {
    int d = blockIdx.x * blockDim.x + threadIdx.x;
    float a1 = 0.f, a2 = 0.f, cB = 0.f, cBf = 0.f;
    for (int e = 0; e < DD; ++e) {
        float wb = WB[e * DD + d];
        float wf = WBf[e * DD + d];
        a1  += w1[e] * wb;
        cB  += Wc[e] * wb;
        a2  += w2[e] * wf;
        cBf += Wc[e] * wf;
    }
    g_vecs[d] = a1; g_vecs[DD + d] = a2;
    g_vecs[2 * DD + d] = cB; g_vecs[3 * DD + d] = cBf;
}

// ---------------------------------------------------------------------------
// K2: gamma + final (fp32 exact dots) + emit u row in fp16 (feeds the GEMM).
// One warp per row.
// ---------------------------------------------------------------------------
__global__ void gamma_final_kernel(const float* __restrict__ u,
                                   const float* __restrict__ w1,
                                   const float* __restrict__ w2,
                                   const float* __restrict__ bias,
                                   const float* __restrict__ Wc,
                                   float* __restrict__ gamma_out,
                                   float* __restrict__ final_out) {
    int row  = blockIdx.x * 8 + (threadIdx.x >> 5);
    int lane = threadIdx.x & 31;
    int t = row & (TT - 1);

    const float* u1 = u + (size_t)row * DD;
    const float* u2 = (t == TT - 1) ? u1 : u1 + DD;
    const float* vS1 = (t == 0)      ? w1 : (g_vecs + 0);
    const float* vCf = (t == 0)      ? Wc : (g_vecs + 2 * DD);
    const float* vS2 = (t == TT - 1) ? w2 : (g_vecs + DD);
    const float* vCb = (t == TT - 1) ? Wc : (g_vecs + 3 * DD);

    float s1 = 0.f, s2 = 0.f, cf = 0.f, cb = 0.f, cu = 0.f;
#pragma unroll
    for (int it = 0; it < 8; ++it) {
        int i = lane * 4 + it * 128;
        float4 uu = *(const float4*)(u1 + i);
        float4 vv = *(const float4*)(u2 + i);
        float4 x1 = *(const float4*)(vS1 + i);
        float4 xc = *(const float4*)(vCf + i);
        float4 wc = *(const float4*)(Wc + i);
        float4 x2 = *(const float4*)(vS2 + i);
        float4 xb = *(const float4*)(vCb + i);
        // fp16 emission of u row (each row visited exactly once as u1)
        union { __half h[4]; uint2 v; } H;
        H.h[0] = __float2half_rn(uu.x);  H.h[1] = __float2half_rn(uu.y);
        H.h[2] = __float2half_rn(uu.z);  H.h[3] = __float2half_rn(uu.w);
        *(uint2*)(g_Af + (size_t)row * DD + i) = H.v;

        s1 += uu.x * x1.x + uu.y * x1.y + uu.z * x1.z + uu.w * x1.w;
        cf += uu.x * xc.x + uu.y * xc.y + uu.z * xc.z + uu.w * xc.w;
        cu += uu.x * wc.x + uu.y * wc.y + uu.z * wc.z + uu.w * wc.w;
        s2 += vv.x * x2.x + vv.y * x2.y + vv.z * x2.z + vv.w * x2.w;
        cb += vv.x * xb.x + vv.y * xb.y + vv.z * xb.z + vv.w * xb.w;
    }
#pragma unroll
    for (int off = 16; off > 0; off >>= 1) {
        s1 += __shfl_down_sync(0xffffffffu, s1, off);
        s2 += __shfl_down_sync(0xffffffffu, s2, off);
        cf += __shfl_down_sync(0xffffffffu, cf, off);
        cb += __shfl_down_sync(0xffffffffu, cb, off);
        cu += __shfl_down_sync(0xffffffffu, cu, off);
    }
    if (lane == 0) {
        float g   = 1.f / (1.f + expf(-(s1 + s2 + bias[0])));
        float fin = 1.f / (1.f + expf(-(g * (cf + cb) + (1.f - g) * cu)));
        g_gamma[row]   = g;
        gamma_out[row] = g;
        final_out[row] = fin;
    }
}

// ---------------------------------------------------------------------------
// K3: fused HMMA GEMM + y epilogue.
// Warps 0-3: C1 = A0(rows bm..bm+127) @ WB[j:j+64]^T
// Warps 4-7: C2 = A1(rows bm+1..bm+128, clamped) @ WBf[j:j+64]^T
// Then y[m, j+c] = g*(xf+xb) + (1-g)*u, xf=(t==0)?u:C1, xb=(t==T-1)?u:C2.
// grid (1024/64 = 16, 32768/128 = 256), 256 threads.
// ---------------------------------------------------------------------------
__global__ __launch_bounds__(256, 1)
void gemm_fused_kernel(const float* __restrict__ u, float* __restrict__ y) {
    extern __shared__ __align__(128) char dsm[];
    const uint32_t sbase = smem_u32(dsm);

    const int tid  = threadIdx.x;
    const int wid  = tid >> 5;
    const int lane = tid & 31;
    const int bm = blockIdx.y * BM;
    const int bj = blockIdx.x * XN;     // V column offset (0..960)

    const int grp = wid >> 2;           // 0: C1, 1: C2
    const int w2  = wid & 3;
    const int wm  = (w2 >> 1) * 64;     // warp m offset (0/64)
    const int wn  = (w2 & 1) * 32;      // warp n offset within 64 (0/32)

    // -- global -> smem loader: 12 cp.async(16B)/thread/stage --
    const int lrow = tid >> 3;          // 0..31 (+j*32)
    const int lchk = tid & 7;
    auto load_stage = [&](int kchunk, int slot) {
        uint32_t sb = sbase + slot * STAGE_BYTES;
        int kb = kchunk * BK;
#pragma unroll
        for (int j = 0; j < 4; ++j) {
            int r = lrow + j * 32;
            uint32_t so = (uint32_t)(r * 128) + (uint32_t)((lchk ^ (r & 7)) << 4);
            int ra1 = bm + 1 + r;  if (ra1 > ROWS - 1) ra1 = ROWS - 1;
            int rb  = bj + r + ((r >> 6) * (DD - XN));   // rows 0-63: WB, 64-127: WBf
            cpasync16(sb + OFF_A0 + so, g_Af + (size_t)(bm + r) * KK + kb + lchk * 8);
            cpasync16(sb + OFF_A1 + so, g_Af + (size_t)ra1 * KK + kb + lchk * 8);
            cpasync16(sb + OFF_B  + so, g_Bf + (size_t)rb * KK + kb + lchk * 8);
        }
    };

    // -- per-thread ldmatrix bases --
    const uint32_t aoff = grp ? OFF_A1 : OFF_A0;
    uint32_t a_base[4], b_base[2];
    int a_rx[4], b_rx[2];
    const int a_ch = lane >> 4;
    const int b_ch = (lane >> 3) & 1;
#pragma unroll
    for (int mi = 0; mi < 4; ++mi) {
        int r = wm + mi * 16 + (lane & 15);
        a_base[mi] = aoff + (uint32_t)(r * 128);
        a_rx[mi] = r & 7;
    }
#pragma unroll
    for (int p = 0; p < 2; ++p) {
        int r = grp * 64 + wn + p * 16 + (lane & 7) + ((lane >> 4) << 3);
        b_base[p] = OFF_B + (uint32_t)(r * 128);
        b_rx[p] = r & 7;
    }

    float acc[4][4][4];
#pragma unroll
    for (int mi = 0; mi < 4; ++mi)
#pragma unroll
        for (int nj = 0; nj < 4; ++nj)
#pragma unroll
            for (int q = 0; q < 4; ++q) acc[mi][nj][q] = 0.f;

    load_stage(0, 0); CP_COMMIT();
    load_stage(1, 1); CP_COMMIT();
    load_stage(2, 2); CP_COMMIT();

    for (int c = 0; c < NCHUNK; ++c) {
        if (c <= NCHUNK - 3)      CP_WAIT_2();
        else if (c == NCHUNK - 2) CP_WAIT_1();
        else                      CP_WAIT_0();
        __syncthreads();

        if (c + 3 < NCHUNK) { load_stage(c + 3, (c + 3) & (STAGES - 1)); CP_COMMIT(); }

        const uint32_t slot = sbase + (uint32_t)((c & (STAGES - 1)) * STAGE_BYTES);

        uint32_t af[2][16], bf[2][8];
#pragma unroll
        for (int mi = 0; mi < 4; ++mi)
            ldm_x4(af[0] + mi * 4, slot + a_base[mi] + (uint32_t)((a_ch ^ a_rx[mi]) << 4));
#pragma unroll
        for (int p = 0; p < 2; ++p)
            ldm_x4(bf[0] + p * 4, slot + b_base[p] + (uint32_t)((b_ch ^ b_rx[p]) << 4));

#pragma unroll
        for (int ks = 0; ks < 4; ++ks) {
            if (ks < 3) {
                int kc = (ks + 1) * 2;
                uint32_t* an  = af[(ks + 1) & 1];
                uint32_t* bn2 = bf[(ks + 1) & 1];
#pragma unroll
                for (int mi = 0; mi < 4; ++mi)
                    ldm_x4(an + mi * 4, slot + a_base[mi] + (uint32_t)(((kc + a_ch) ^ a_rx[mi]) << 4));
#pragma unroll
                for (int p = 0; p < 2; ++p)
                    ldm_x4(bn2 + p * 4, slot + b_base[p] + (uint32_t)(((kc + b_ch) ^ b_rx[p]) << 4));
            }
            const uint32_t* a = af[ks & 1];
            const uint32_t* b = bf[ks & 1];
#pragma unroll
            for (int mi = 0; mi < 4; ++mi)
#pragma unroll
                for (int nj = 0; nj < 4; ++nj)
                    mma16816(acc[mi][nj], a + mi * 4, b + nj * 2);
        }
        __syncthreads();
    }

    // -- epilogue: stage C1/C2 (fp32) + gamma to smem, then write y --
    float* Cs = (float*)dsm;                       // [2][128][CS_STRIDE]
    float* Gs = Cs + 2 * 128 * CS_STRIDE;          // [128]
    const int lr = lane >> 2;
    const int lc = (lane & 3) * 2;
    float* Cg = Cs + (size_t)grp * 128 * CS_STRIDE;
#pragma unroll
    for (int mi = 0; mi < 4; ++mi) {
#pragma unroll
        for (int nj = 0; nj < 4; ++nj) {
            float* p0 = Cg + (size_t)(wm + mi * 16 + lr) * CS_STRIDE + wn + nj * 8 + lc;
            *(float2*)p0                    = make_float2(acc[mi][nj][0], acc[mi][nj][1]);
            *(float2*)(p0 + 8 * CS_STRIDE)  = make_float2(acc[mi][nj][2], acc[mi][nj][3]);
        }
    }
    if (tid < 128) Gs[tid] = g_gamma[bm + tid];
    __syncthreads();

#pragma unroll
    for (int it = 0; it < 8; ++it) {
        int idx = tid + it * 256;          // 0..2047  (128 rows x 16 col-quads)
        int row = idx >> 4;
        int c4  = (idx & 15) * 4;
        int m = bm + row;
        int t = m & (TT - 1);
        float g  = Gs[row];
        float og = 1.f - g;

        float4 uu = *(const float4*)(u + (size_t)m * DD + bj + c4);
        float4 c1 = *(const float4*)(Cs + (size_t)row * CS_STRIDE + c4);
        float4 c2 = *(const float4*)(Cs + (size_t)(128 + row) * CS_STRIDE + c4);
        float4 xf = (t == 0)      ? uu : c1;
        float4 xb = (t == TT - 1) ? uu : c2;

        float4 out;
        out.x = g * (xf.x + xb.x) + og * uu.x;
        out.y = g * (xf.y + xb.y) + og * uu.y;
        out.z = g * (xf.z + xb.z) + og * uu.z;
        out.w = g * (xf.w + xb.w) + og * uu.w;
        *(float4*)(y + (size_t)m * DD + bj + c4) = out;
    }
}

// ---------------------------------------------------------------------------
// kernel_launch: inputs 0:u 1:WA(dead) 2:WB 3:WAf(dead) 4:WBf 5:w1 6:w2 7:b 8:Wc
// Output: [y | gamma | final] flattened f32.
// ---------------------------------------------------------------------------
extern "C" void kernel_launch(void* const* d_in, const int* in_sizes, int n_in,
                              void* d_out, int out_size) {
    (void)in_sizes; (void)n_in; (void)out_size;
    const float* u   = (const float*)d_in[0];
    const float* WB  = (const float*)d_in[2];
    const float* WBf = (const float*)d_in[4];
    const float* w1  = (const float*)d_in[5];
    const float* w2  = (const float*)d_in[6];
    const float* b   = (const float*)d_in[7];
    const float* Wc  = (const float*)d_in[8];

    float* y         = (float*)d_out;
    float* gamma_out = y + Y_ELEMS;
    float* final_out = gamma_out + G_ELEMS;

    cudaFuncSetAttribute(gemm_fused_kernel,
                         cudaFuncAttributeMaxDynamicSharedMemorySize, SMEM_DYN);

    convert_w_kernel<<<(2 * DD * KK) / 1024, 256>>>(WB, WBf);
    precompute_vectors_kernel<<<DD / 256, 256>>>(WB, WBf, w1, w2, Wc);
    gamma_final_kernel<<<ROWS / 8, 256>>>(u, w1, w2, b, Wc, gamma_out, final_out);
    gemm_fused_kernel<<<dim3(DD / XN, ROWS / BM), 256, SMEM_DYN>>>(u, y);
}

// round 10
// speedup vs baseline: 5.1756x; 1.1868x over previous
#include <cuda_runtime.h>
#include <cuda_fp16.h>
#include <math.h>
#include <stdint.h>

// ---------------------------------------------------------------------------
// Problem: u (8,4096,1024) f32. Outputs: y (8,4096,1024), gamma, final.
// gamma kernel emits u in fp16; fused GEMM computes
//   C1[m] = u[m]   @ WB ^T (cols bj..bj+63)   (warps 0-3)
//   C2[m] = u[m+1] @ WBf^T (cols bj..bj+63)   (warps 4-7, +1 row shift)
// from ONE shared 129-row A tile, then writes y = g*(xf+xb)+(1-g)*u directly.
// 3-stage cp.async pipeline, 99KB SMEM -> 2 CTAs/SM (4 warps/SMSP).
// ---------------------------------------------------------------------------
#define BB 8
#define TT 4096
#define DD 1024
#define ROWS (BB * TT)              // 32768  (M)
#define KK   DD                     // 1024   (K)
#define Y_ELEMS   (ROWS * DD)
#define G_ELEMS   (ROWS)

// GEMM tiling
#define BM 128
#define XN 64                        // V-columns per CTA (each of C1, C2)
#define BK 64
#define STAGES 3
#define NCHUNK (KK / BK)             // 16
#define OFF_A 0                      // 129 rows x 128B (pad to 130)
#define OFF_B 16640
#define STAGE_BYTES 33024            // A(16640) + B(16384)
#define SMEM_DYN (STAGES * STAGE_BYTES)   // 99072
#define CS_STRIDE 68                 // fp32 staging stride (bank-friendly)

// Device-global scratch (no cudaMalloc anywhere)
__device__ __half g_Af[(size_t)ROWS * KK];       // 64 MiB  (u in fp16)
__device__ __half g_Bf[(size_t)2 * DD * KK];     // 4 MiB: rows 0..1023 WB, 1024.. WBf
__device__ float  g_vecs[4 * DD];                // a1 | a2 | cB | cBf
__device__ float  g_gamma[ROWS];

// ---------------------------------------------------------------------------
// PTX helpers (sm_80-class only: cp.async, ldmatrix, mma.sync)
// ---------------------------------------------------------------------------
__device__ __forceinline__ uint32_t smem_u32(const void* p) {
    uint32_t a;
    asm("{ .reg .u64 t; cvta.to.shared.u64 t, %1; cvt.u32.u64 %0, t; }"
        : "=r"(a) : "l"(p));
    return a;
}
__device__ __forceinline__ void cpasync16(uint32_t dst, const void* src) {
    asm volatile("cp.async.cg.shared.global [%0], [%1], 16;" :: "r"(dst), "l"(src));
}
#define CP_COMMIT() asm volatile("cp.async.commit_group;" ::: "memory")
#define CP_WAIT_2() asm volatile("cp.async.wait_group 2;" ::: "memory")
#define CP_WAIT_1() asm volatile("cp.async.wait_group 1;" ::: "memory")
#define CP_WAIT_0() asm volatile("cp.async.wait_group 0;" ::: "memory")

__device__ __forceinline__ void ldm_x4(uint32_t* r, uint32_t addr) {
    asm volatile("ldmatrix.sync.aligned.m8n8.x4.shared.b16 {%0,%1,%2,%3}, [%4];"
                 : "=r"(r[0]), "=r"(r[1]), "=r"(r[2]), "=r"(r[3]) : "r"(addr));
}
__device__ __forceinline__ void mma16816(float* c, const uint32_t* a,
                                         const uint32_t* b) {
    asm volatile("mma.sync.aligned.m16n8k16.row.col.f32.f16.f16.f32 "
                 "{%0,%1,%2,%3}, {%4,%5,%6,%7}, {%8,%9}, {%0,%1,%2,%3};"
                 : "+f"(c[0]), "+f"(c[1]), "+f"(c[2]), "+f"(c[3])
                 : "r"(a[0]), "r"(a[1]), "r"(a[2]), "r"(a[3]),
                   "r"(b[0]), "r"(b[1]));
}

// ---------------------------------------------------------------------------
// K0: [WB;WBf] -> fp16.
// ---------------------------------------------------------------------------
__global__ void convert_w_kernel(const float* __restrict__ WB,
                                 const float* __restrict__ WBf) {
    size_t i = ((size_t)blockIdx.x * 256 + threadIdx.x) * 4;
    const float* src = (i < (size_t)DD * DD) ? (WB + i) : (WBf + i - (size_t)DD * DD);
    float4 x = *(const float4*)src;
    union { __half h[4]; uint2 v; } H;
    H.h[0] = __float2half_rn(x.x);  H.h[1] = __float2half_rn(x.y);
    H.h[2] = __float2half_rn(x.z);  H.h[3] = __float2half_rn(x.w);
    *(uint2*)(g_Bf + i) = H.v;
}

// ---------------------------------------------------------------------------
// K1: precompute a1 = w1@WB, a2 = w2@WBf, cB = Wc@WB, cBf = Wc@WBf (fp32 exact)
// ---------------------------------------------------------------------------
__global__ void precompute_vectors_kernel(const float* __restrict__ WB,
                                          const float* __restrict__ WBf,
                                          const float* __restrict__ w1,
                                          const float* __restrict__ w2,
                                          const float* __restrict__ Wc) {
    int d = blockIdx.x * blockDim.x + threadIdx.x;
    float a1 = 0.f, a2 = 0.f, cB = 0.f, cBf = 0.f;
    for (int e = 0; e < DD; ++e) {
        float wb = WB[e * DD + d];
        float wf = WBf[e * DD + d];
        a1  += w1[e] * wb;
        cB  += Wc[e] * wb;
        a2  += w2[e] * wf;
        cBf += Wc[e] * wf;
    }
    g_vecs[d] = a1; g_vecs[DD + d] = a2;
    g_vecs[2 * DD + d] = cB; g_vecs[3 * DD + d] = cBf;
}

// ---------------------------------------------------------------------------
// K2: gamma + final (fp32 exact dots) + emit u row in fp16 (feeds the GEMM).
// One warp per row.
// ---------------------------------------------------------------------------
__global__ void gamma_final_kernel(const float* __restrict__ u,
                                   const float* __restrict__ w1,
                                   const float* __restrict__ w2,
                                   const float* __restrict__ bias,
                                   const float* __restrict__ Wc,
                                   float* __restrict__ gamma_out,
                                   float* __restrict__ final_out) {
    int row  = blockIdx.x * 8 + (threadIdx.x >> 5);
    int lane = threadIdx.x & 31;
    int t = row & (TT - 1);

    const float* u1 = u + (size_t)row * DD;
    const float* u2 = (t == TT - 1) ? u1 : u1 + DD;
    const float* vS1 = (t == 0)      ? w1 : (g_vecs + 0);
    const float* vCf = (t == 0)      ? Wc : (g_vecs + 2 * DD);
    const float* vS2 = (t == TT - 1) ? w2 : (g_vecs + DD);
    const float* vCb = (t == TT - 1) ? Wc : (g_vecs + 3 * DD);

    float s1 = 0.f, s2 = 0.f, cf = 0.f, cb = 0.f, cu = 0.f;
#pragma unroll
    for (int it = 0; it < 8; ++it) {
        int i = lane * 4 + it * 128;
        float4 uu = *(const float4*)(u1 + i);
        float4 vv = *(const float4*)(u2 + i);
        float4 x1 = *(const float4*)(vS1 + i);
        float4 xc = *(const float4*)(vCf + i);
        float4 wc = *(const float4*)(Wc + i);
        float4 x2 = *(const float4*)(vS2 + i);
        float4 xb = *(const float4*)(vCb + i);
        union { __half h[4]; uint2 v; } H;
        H.h[0] = __float2half_rn(uu.x);  H.h[1] = __float2half_rn(uu.y);
        H.h[2] = __float2half_rn(uu.z);  H.h[3] = __float2half_rn(uu.w);
        *(uint2*)(g_Af + (size_t)row * DD + i) = H.v;

        s1 += uu.x * x1.x + uu.y * x1.y + uu.z * x1.z + uu.w * x1.w;
        cf += uu.x * xc.x + uu.y * xc.y + uu.z * xc.z + uu.w * xc.w;
        cu += uu.x * wc.x + uu.y * wc.y + uu.z * wc.z + uu.w * wc.w;
        s2 += vv.x * x2.x + vv.y * x2.y + vv.z * x2.z + vv.w * x2.w;
        cb += vv.x * xb.x + vv.y * xb.y + vv.z * xb.z + vv.w * xb.w;
    }
#pragma unroll
    for (int off = 16; off > 0; off >>= 1) {
        s1 += __shfl_down_sync(0xffffffffu, s1, off);
        s2 += __shfl_down_sync(0xffffffffu, s2, off);
        cf += __shfl_down_sync(0xffffffffu, cf, off);
        cb += __shfl_down_sync(0xffffffffu, cb, off);
        cu += __shfl_down_sync(0xffffffffu, cu, off);
    }
    if (lane == 0) {
        float g   = 1.f / (1.f + expf(-(s1 + s2 + bias[0])));
        float fin = 1.f / (1.f + expf(-(g * (cf + cb) + (1.f - g) * cu)));
        g_gamma[row]   = g;
        gamma_out[row] = g;
        final_out[row] = fin;
    }
}

// ---------------------------------------------------------------------------
// K3: fused HMMA GEMM + y epilogue. 256 threads, 2 CTAs/SM.
// Shared A tile of 129 rows (bm..bm+128, clamped); warps 4-7 use row+1.
// grid (1024/64 = 16, 32768/128 = 256).
// ---------------------------------------------------------------------------
__global__ __launch_bounds__(256, 2)
void gemm_fused_kernel(const float* __restrict__ u, float* __restrict__ y) {
    extern __shared__ __align__(128) char dsm[];
    const uint32_t sbase = smem_u32(dsm);

    const int tid  = threadIdx.x;
    const int wid  = tid >> 5;
    const int lane = tid & 31;
    const int bm = blockIdx.y * BM;
    const int bj = blockIdx.x * XN;     // V column offset (0..960)

    const int grp = wid >> 2;           // 0: C1 (row m), 1: C2 (row m+1)
    const int w2  = wid & 3;
    const int wm  = (w2 >> 1) * 64;     // warp m offset (0/64)
    const int wn  = (w2 & 1) * 32;      // warp n offset within 64 (0/32)

    // -- global -> smem loader: 8 cp.async/thread + 1 extra row by 8 threads --
    const int lrow = tid >> 3;          // 0..31 (+j*32)
    const int lchk = tid & 7;
    auto load_stage = [&](int kchunk, int slot) {
        uint32_t sb = sbase + slot * STAGE_BYTES;
        int kb = kchunk * BK;
#pragma unroll
        for (int j = 0; j < 4; ++j) {
            int r = lrow + j * 32;
            uint32_t so = (uint32_t)(r * 128) + (uint32_t)((lchk ^ (r & 7)) << 4);
            int rb = bj + r + ((r >> 6) * (DD - XN));   // rows 0-63: WB, 64-127: WBf
            cpasync16(sb + OFF_A + so, g_Af + (size_t)(bm + r) * KK + kb + lchk * 8);
            cpasync16(sb + OFF_B + so, g_Bf + (size_t)rb * KK + kb + lchk * 8);
        }
        if (tid < 8) {                  // A row 128 (clamped at last CTA)
            int ra = bm + 128;  if (ra > ROWS - 1) ra = ROWS - 1;
            cpasync16(sb + OFF_A + 128 * 128 + tid * 16,
                      g_Af + (size_t)ra * KK + kb + tid * 8);
        }
    };

    // -- per-thread ldmatrix bases (A row gets +grp shift) --
    uint32_t a_base[4], b_base[2];
    int a_rx[4], b_rx[2];
    const int a_ch = lane >> 4;
    const int b_ch = (lane >> 3) & 1;
#pragma unroll
    for (int mi = 0; mi < 4; ++mi) {
        int r = wm + mi * 16 + (lane & 15) + grp;
        a_base[mi] = OFF_A + (uint32_t)(r * 128);
        a_rx[mi] = r & 7;
    }
#pragma unroll
    for (int p = 0; p < 2; ++p) {
        int r = grp * 64 + wn + p * 16 + (lane & 7) + ((lane >> 4) << 3);
        b_base[p] = OFF_B + (uint32_t)(r * 128);
        b_rx[p] = r & 7;
    }

    float acc[4][4][4];
#pragma unroll
    for (int mi = 0; mi < 4; ++mi)
#pragma unroll
        for (int nj = 0; nj < 4; ++nj)
#pragma unroll
            for (int q = 0; q < 4; ++q) acc[mi][nj][q] = 0.f;

    load_stage(0, 0); CP_COMMIT();
    load_stage(1, 1); CP_COMMIT();

    for (int c = 0; c < NCHUNK; ++c) {
        if (c + 2 < NCHUNK) {
            load_stage(c + 2, (c + 2) % STAGES);
            CP_COMMIT();
            CP_WAIT_2();
        } else if (c + 1 < NCHUNK) {
            CP_WAIT_1();
        } else {
            CP_WAIT_0();
        }
        __syncthreads();

        const uint32_t slot = sbase + (uint32_t)((c % STAGES) * STAGE_BYTES);

#pragma unroll
        for (int ks = 0; ks < 4; ++ks) {
            const int kc = ks * 2;
            uint32_t af[16], bf[8];
#pragma unroll
            for (int mi = 0; mi < 4; ++mi)
                ldm_x4(af + mi * 4, slot + a_base[mi] + (uint32_t)(((kc + a_ch) ^ a_rx[mi]) << 4));
#pragma unroll
            for (int p = 0; p < 2; ++p)
                ldm_x4(bf + p * 4, slot + b_base[p] + (uint32_t)(((kc + b_ch) ^ b_rx[p]) << 4));
#pragma unroll
            for (int mi = 0; mi < 4; ++mi)
#pragma unroll
                for (int nj = 0; nj < 4; ++nj)
                    mma16816(acc[mi][nj], af + mi * 4, bf + nj * 2);
        }
        __syncthreads();   // protect slot (c+3)%3 == c%3 from next-iter loads
    }

    // -- epilogue: stage C1/C2 (fp32) + gamma to smem, then write y --
    float* Cs = (float*)dsm;                       // [2][128][CS_STRIDE]
    float* Gs = Cs + 2 * 128 * CS_STRIDE;          // [128]
    const int lr = lane >> 2;
    const int lc = (lane & 3) * 2;
    float* Cg = Cs + (size_t)grp * 128 * CS_STRIDE;
#pragma unroll
    for (int mi = 0; mi < 4; ++mi) {
#pragma unroll
        for (int nj = 0; nj < 4; ++nj) {
            float* p0 = Cg + (size_t)(wm + mi * 16 + lr) * CS_STRIDE + wn + nj * 8 + lc;
            *(float2*)p0                    = make_float2(acc[mi][nj][0], acc[mi][nj][1]);
            *(float2*)(p0 + 8 * CS_STRIDE)  = make_float2(acc[mi][nj][2], acc[mi][nj][3]);
        }
    }
    if (tid < 128) Gs[tid] = g_gamma[bm + tid];
    __syncthreads();

#pragma unroll
    for (int it = 0; it < 8; ++it) {
        int idx = tid + it * 256;          // 0..2047  (128 rows x 16 col-quads)
        int row = idx >> 4;
        int c4  = (idx & 15) * 4;
        int m = bm + row;
        int t = m & (TT - 1);
        float g  = Gs[row];
        float og = 1.f - g;

        float4 uu = *(const float4*)(u + (size_t)m * DD + bj + c4);
        float4 c1 = *(const float4*)(Cs + (size_t)row * CS_STRIDE + c4);
        float4 c2 = *(const float4*)(Cs + (size_t)(128 + row) * CS_STRIDE + c4);
        float4 xf = (t == 0)      ? uu : c1;
        float4 xb = (t == TT - 1) ? uu : c2;

        float4 out;
        out.x = g * (xf.x + xb.x) + og * uu.x;
        out.y = g * (xf.y + xb.y) + og * uu.y;
        out.z = g * (xf.z + xb.z) + og * uu.z;
        out.w = g * (xf.w + xb.w) + og * uu.w;
        *(float4*)(y + (size_t)m * DD + bj + c4) = out;
    }
}

// ---------------------------------------------------------------------------
// kernel_launch: inputs 0:u 1:WA(dead) 2:WB 3:WAf(dead) 4:WBf 5:w1 6:w2 7:b 8:Wc
// Output: [y | gamma | final] flattened f32.
// ---------------------------------------------------------------------------
extern "C" void kernel_launch(void* const* d_in, const int* in_sizes, int n_in,
                              void* d_out, int out_size) {
    (void)in_sizes; (void)n_in; (void)out_size;
    const float* u   = (const float*)d_in[0];
    const float* WB  = (const float*)d_in[2];
    const float* WBf = (const float*)d_in[4];
    const float* w1  = (const float*)d_in[5];
    const float* w2  = (const float*)d_in[6];
    const float* b   = (const float*)d_in[7];
    const float* Wc  = (const float*)d_in[8];

    float* y         = (float*)d_out;
    float* gamma_out = y + Y_ELEMS;
    float* final_out = gamma_out + G_ELEMS;

    cudaFuncSetAttribute(gemm_fused_kernel,
                         cudaFuncAttributeMaxDynamicSharedMemorySize, SMEM_DYN);

    convert_w_kernel<<<(2 * DD * KK) / 1024, 256>>>(WB, WBf);
    precompute_vectors_kernel<<<DD / 256, 256>>>(WB, WBf, w1, w2, Wc);
    gamma_final_kernel<<<ROWS / 8, 256>>>(u, w1, w2, b, Wc, gamma_out, final_out);
    gemm_fused_kernel<<<dim3(DD / XN, ROWS / BM), 256, SMEM_DYN>>>(u, y);
}

// round 11
// speedup vs baseline: 5.1890x; 1.0026x over previous
#include <cuda_runtime.h>
#include <cuda_fp16.h>
#include <math.h>
#include <stdint.h>

// ---------------------------------------------------------------------------
// Problem: u (8,4096,1024) f32. Outputs: y (8,4096,1024), gamma, final.
// gamma kernel emits u in fp16; fused GEMM computes
//   C1[m] = u[m]   @ WB ^T (cols bj..bj+63)   (warps 0-3)
//   C2[m] = u[m+1] @ WBf^T (cols bj..bj+63)   (warps 4-7, +1 row shift)
// from ONE shared 129-row A tile, then writes y = g*(xf+xb)+(1-g)*u directly.
// 3-stage cp.async pipeline, ONE barrier per chunk, 2 CTAs/SM.
// ---------------------------------------------------------------------------
#define BB 8
#define TT 4096
#define DD 1024
#define ROWS (BB * TT)              // 32768  (M)
#define KK   DD                     // 1024   (K)
#define Y_ELEMS   (ROWS * DD)
#define G_ELEMS   (ROWS)

// GEMM tiling
#define BM 128
#define XN 64                        // V-columns per CTA (each of C1, C2)
#define BK 64
#define STAGES 3
#define NCHUNK (KK / BK)             // 16
#define OFF_A 0                      // 129 rows x 128B
#define OFF_B 16640
#define STAGE_BYTES 33024            // A(16640) + B(16384)
#define SMEM_DYN (STAGES * STAGE_BYTES)   // 99072
#define CS_STRIDE 68                 // fp32 staging stride (bank-friendly)

// Device-global scratch (no cudaMalloc anywhere)
__device__ __half g_Af[(size_t)ROWS * KK];       // 64 MiB  (u in fp16)
__device__ __half g_Bf[(size_t)2 * DD * KK];     // 4 MiB: rows 0..1023 WB, 1024.. WBf
__device__ float  g_vecs[4 * DD];                // a1 | a2 | cB | cBf
__device__ float  g_gamma[ROWS];

// ---------------------------------------------------------------------------
// PTX helpers (sm_80-class only: cp.async, ldmatrix, mma.sync)
// ---------------------------------------------------------------------------
__device__ __forceinline__ uint32_t smem_u32(const void* p) {
    uint32_t a;
    asm("{ .reg .u64 t; cvta.to.shared.u64 t, %1; cvt.u32.u64 %0, t; }"
        : "=r"(a) : "l"(p));
    return a;
}
__device__ __forceinline__ void cpasync16(uint32_t dst, const void* src) {
    asm volatile("cp.async.cg.shared.global [%0], [%1], 16;" :: "r"(dst), "l"(src));
}
#define CP_COMMIT() asm volatile("cp.async.commit_group;" ::: "memory")
#define CP_WAIT_1() asm volatile("cp.async.wait_group 1;" ::: "memory")
#define CP_WAIT_0() asm volatile("cp.async.wait_group 0;" ::: "memory")

__device__ __forceinline__ void ldm_x4(uint32_t* r, uint32_t addr) {
    asm volatile("ldmatrix.sync.aligned.m8n8.x4.shared.b16 {%0,%1,%2,%3}, [%4];"
                 : "=r"(r[0]), "=r"(r[1]), "=r"(r[2]), "=r"(r[3]) : "r"(addr));
}
__device__ __forceinline__ void mma16816(float* c, const uint32_t* a,
                                         const uint32_t* b) {
    asm volatile("mma.sync.aligned.m16n8k16.row.col.f32.f16.f16.f32 "
                 "{%0,%1,%2,%3}, {%4,%5,%6,%7}, {%8,%9}, {%0,%1,%2,%3};"
                 : "+f"(c[0]), "+f"(c[1]), "+f"(c[2]), "+f"(c[3])
                 : "r"(a[0]), "r"(a[1]), "r"(a[2]), "r"(a[3]),
                   "r"(b[0]), "r"(b[1]));
}

// ---------------------------------------------------------------------------
// K0: [WB;WBf] -> fp16.
// ---------------------------------------------------------------------------
__global__ void convert_w_kernel(const float* __restrict__ WB,
                                 const float* __restrict__ WBf) {
    size_t i = ((size_t)blockIdx.x * 256 + threadIdx.x) * 4;
    const float* src = (i < (size_t)DD * DD) ? (WB + i) : (WBf + i - (size_t)DD * DD);
    float4 x = *(const float4*)src;
    union { __half h[4]; uint2 v; } H;
    H.h[0] = __float2half_rn(x.x);  H.h[1] = __float2half_rn(x.y);
    H.h[2] = __float2half_rn(x.z);  H.h[3] = __float2half_rn(x.w);
    *(uint2*)(g_Bf + i) = H.v;
}

// ---------------------------------------------------------------------------
// K1: precompute a1 = w1@WB, a2 = w2@WBf, cB = Wc@WB, cBf = Wc@WBf (fp32 exact)
// ---------------------------------------------------------------------------
__global__ void precompute_vectors_kernel(const float* __restrict__ WB,
                                          const float* __restrict__ WBf,
                                          const float* __restrict__ w1,
                                          const float* __restrict__ w2,
                                          const float* __restrict__ Wc) {
    int d = blockIdx.x * blockDim.x + threadIdx.x;
    float a1 = 0.f, a2 = 0.f, cB = 0.f, cBf = 0.f;
    for (int e = 0; e < DD; ++e) {
        float wb = WB[e * DD + d];
        float wf = WBf[e * DD + d];
        a1  += w1[e] * wb;
        cB  += Wc[e] * wb;
        a2  += w2[e] * wf;
        cBf += Wc[e] * wf;
    }
    g_vecs[d] = a1; g_vecs[DD + d] = a2;
    g_vecs[2 * DD + d] = cB; g_vecs[3 * DD + d] = cBf;
}

// ---------------------------------------------------------------------------
// K2: gamma + final (fp32 exact dots) + emit u row in fp16 (feeds the GEMM).
// One warp per row.
// ---------------------------------------------------------------------------
__global__ void gamma_final_kernel(const float* __restrict__ u,
                                   const float* __restrict__ w1,
                                   const float* __restrict__ w2,
                                   const float* __restrict__ bias,
                                   const float* __restrict__ Wc,
                                   float* __restrict__ gamma_out,
                                   float* __restrict__ final_out) {
    int row  = blockIdx.x * 8 + (threadIdx.x >> 5);
    int lane = threadIdx.x & 31;
    int t = row & (TT - 1);

    const float* u1 = u + (size_t)row * DD;
    const float* u2 = (t == TT - 1) ? u1 : u1 + DD;
    const float* vS1 = (t == 0)      ? w1 : (g_vecs + 0);
    const float* vCf = (t == 0)      ? Wc : (g_vecs + 2 * DD);
    const float* vS2 = (t == TT - 1) ? w2 : (g_vecs + DD);
    const float* vCb = (t == TT - 1) ? Wc : (g_vecs + 3 * DD);

    float s1 = 0.f, s2 = 0.f, cf = 0.f, cb = 0.f, cu = 0.f;
#pragma unroll
    for (int it = 0; it < 8; ++it) {
        int i = lane * 4 + it * 128;
        float4 uu = *(const float4*)(u1 + i);
        float4 vv = *(const float4*)(u2 + i);
        float4 x1 = *(const float4*)(vS1 + i);
        float4 xc = *(const float4*)(vCf + i);
        float4 wc = *(const float4*)(Wc + i);
        float4 x2 = *(const float4*)(vS2 + i);
        float4 xb = *(const float4*)(vCb + i);
        union { __half h[4]; uint2 v; } H;
        H.h[0] = __float2half_rn(uu.x);  H.h[1] = __float2half_rn(uu.y);
        H.h[2] = __float2half_rn(uu.z);  H.h[3] = __float2half_rn(uu.w);
        *(uint2*)(g_Af + (size_t)row * DD + i) = H.v;

        s1 += uu.x * x1.x + uu.y * x1.y + uu.z * x1.z + uu.w * x1.w;
        cf += uu.x * xc.x + uu.y * xc.y + uu.z * xc.z + uu.w * xc.w;
        cu += uu.x * wc.x + uu.y * wc.y + uu.z * wc.z + uu.w * wc.w;
        s2 += vv.x * x2.x + vv.y * x2.y + vv.z * x2.z + vv.w * x2.w;
        cb += vv.x * xb.x + vv.y * xb.y + vv.z * xb.z + vv.w * xb.w;
    }
#pragma unroll
    for (int off = 16; off > 0; off >>= 1) {
        s1 += __shfl_down_sync(0xffffffffu, s1, off);
        s2 += __shfl_down_sync(0xffffffffu, s2, off);
        cf += __shfl_down_sync(0xffffffffu, cf, off);
        cb += __shfl_down_sync(0xffffffffu, cb, off);
        cu += __shfl_down_sync(0xffffffffu, cu, off);
    }
    if (lane == 0) {
        float g   = 1.f / (1.f + expf(-(s1 + s2 + bias[0])));
        float fin = 1.f / (1.f + expf(-(g * (cf + cb) + (1.f - g) * cu)));
        g_gamma[row]   = g;
        gamma_out[row] = g;
        final_out[row] = fin;
    }
}

// ---------------------------------------------------------------------------
// K3: fused HMMA GEMM + y epilogue. 256 threads, 2 CTAs/SM, ONE barrier/chunk.
// Per chunk c:  wait(g_c) -> sync -> issue loads for slot (c+2)%3 -> compute.
// Write target slot (c+2)%3 == (c-1)%3 was last read in chunk c-1, which all
// warps finished before this chunk's barrier -> WAR-safe with one barrier.
// grid (1024/64 = 16, 32768/128 = 256).
// ---------------------------------------------------------------------------
__global__ __launch_bounds__(256, 2)
void gemm_fused_kernel(const float* __restrict__ u, float* __restrict__ y) {
    extern __shared__ __align__(128) char dsm[];
    const uint32_t sbase = smem_u32(dsm);

    const int tid  = threadIdx.x;
    const int wid  = tid >> 5;
    const int lane = tid & 31;
    const int bm = blockIdx.y * BM;
    const int bj = blockIdx.x * XN;     // V column offset (0..960)

    const int grp = wid >> 2;           // 0: C1 (row m), 1: C2 (row m+1)
    const int w2  = wid & 3;
    const int wm  = (w2 >> 1) * 64;     // warp m offset (0/64)
    const int wn  = (w2 & 1) * 32;      // warp n offset within 64 (0/32)

    // -- global -> smem loader: 8 cp.async/thread + 1 extra row by 8 threads --
    const int lrow = tid >> 3;          // 0..31 (+j*32)
    const int lchk = tid & 7;
    auto load_stage = [&](int kchunk, int slot) {
        uint32_t sb = sbase + slot * STAGE_BYTES;
        int kb = kchunk * BK;
#pragma unroll
        for (int j = 0; j < 4; ++j) {
            int r = lrow + j * 32;
            uint32_t so = (uint32_t)(r * 128) + (uint32_t)((lchk ^ (r & 7)) << 4);
            int rb = bj + r + ((r >> 6) * (DD - XN));   // rows 0-63: WB, 64-127: WBf
            cpasync16(sb + OFF_A + so, g_Af + (size_t)(bm + r) * KK + kb + lchk * 8);
            cpasync16(sb + OFF_B + so, g_Bf + (size_t)rb * KK + kb + lchk * 8);
        }
        if (tid < 8) {                  // A row 128 (clamped at last CTA)
            int ra = bm + 128;  if (ra > ROWS - 1) ra = ROWS - 1;
            cpasync16(sb + OFF_A + 128 * 128 + tid * 16,
                      g_Af + (size_t)ra * KK + kb + tid * 8);
        }
    };

    // -- per-thread ldmatrix bases (A row gets +grp shift) --
    uint32_t a_base[4], b_base[2];
    int a_rx[4], b_rx[2];
    const int a_ch = lane >> 4;
    const int b_ch = (lane >> 3) & 1;
#pragma unroll
    for (int mi = 0; mi < 4; ++mi) {
        int r = wm + mi * 16 + (lane & 15) + grp;
        a_base[mi] = OFF_A + (uint32_t)(r * 128);
        a_rx[mi] = r & 7;
    }
#pragma unroll
    for (int p = 0; p < 2; ++p) {
        int r = grp * 64 + wn + p * 16 + (lane & 7) + ((lane >> 4) << 3);
        b_base[p] = OFF_B + (uint32_t)(r * 128);
        b_rx[p] = r & 7;
    }

    float acc[4][4][4];
#pragma unroll
    for (int mi = 0; mi < 4; ++mi)
#pragma unroll
        for (int nj = 0; nj < 4; ++nj)
#pragma unroll
            for (int q = 0; q < 4; ++q) acc[mi][nj][q] = 0.f;

    load_stage(0, 0); CP_COMMIT();
    load_stage(1, 1); CP_COMMIT();

    for (int c = 0; c < NCHUNK; ++c) {
        // need group c complete; the only younger group is c+1 (if issued)
        if (c < NCHUNK - 1) CP_WAIT_1(); else CP_WAIT_0();
        __syncthreads();

        if (c + 2 < NCHUNK) {
            load_stage(c + 2, (c + 2) % STAGES);
            CP_COMMIT();
        }

        const uint32_t slot = sbase + (uint32_t)((c % STAGES) * STAGE_BYTES);

#pragma unroll
        for (int ks = 0; ks < 4; ++ks) {
            const int kc = ks * 2;
            uint32_t af[16], bf[8];
#pragma unroll
            for (int mi = 0; mi < 4; ++mi)
                ldm_x4(af + mi * 4, slot + a_base[mi] + (uint32_t)(((kc + a_ch) ^ a_rx[mi]) << 4));
#pragma unroll
            for (int p = 0; p < 2; ++p)
                ldm_x4(bf + p * 4, slot + b_base[p] + (uint32_t)(((kc + b_ch) ^ b_rx[p]) << 4));
#pragma unroll
            for (int mi = 0; mi < 4; ++mi)
#pragma unroll
                for (int nj = 0; nj < 4; ++nj)
                    mma16816(acc[mi][nj], af + mi * 4, bf + nj * 2);
        }
    }
    __syncthreads();   // everyone done reading SMEM before Cs staging reuses it

    // -- epilogue: stage C1/C2 (fp32) + gamma to smem, then write y --
    float* Cs = (float*)dsm;                       // [2][128][CS_STRIDE]
    float* Gs = Cs + 2 * 128 * CS_STRIDE;          // [128]
    const int lr = lane >> 2;
    const int lc = (lane & 3) * 2;
    float* Cg = Cs + (size_t)grp * 128 * CS_STRIDE;
#pragma unroll
    for (int mi = 0; mi < 4; ++mi) {
#pragma unroll
        for (int nj = 0; nj < 4; ++nj) {
            float* p0 = Cg + (size_t)(wm + mi * 16 + lr) * CS_STRIDE + wn + nj * 8 + lc;
            *(float2*)p0                    = make_float2(acc[mi][nj][0], acc[mi][nj][1]);
            *(float2*)(p0 + 8 * CS_STRIDE)  = make_float2(acc[mi][nj][2], acc[mi][nj][3]);
        }
    }
    if (tid < 128) Gs[tid] = g_gamma[bm + tid];
    __syncthreads();

#pragma unroll
    for (int it = 0; it < 8; ++it) {
        int idx = tid + it * 256;          // 0..2047  (128 rows x 16 col-quads)
        int row = idx >> 4;
        int c4  = (idx & 15) * 4;
        int m = bm + row;
        int t = m & (TT - 1);
        float g  = Gs[row];
        float og = 1.f - g;

        float4 uu = *(const float4*)(u + (size_t)m * DD + bj + c4);
        float4 c1 = *(const float4*)(Cs + (size_t)row * CS_STRIDE + c4);
        float4 c2 = *(const float4*)(Cs + (size_t)(128 + row) * CS_STRIDE + c4);
        float4 xf = (t == 0)      ? uu : c1;
        float4 xb = (t == TT - 1) ? uu : c2;

        float4 out;
        out.x = g * (xf.x + xb.x) + og * uu.x;
        out.y = g * (xf.y + xb.y) + og * uu.y;
        out.z = g * (xf.z + xb.z) + og * uu.z;
        out.w = g * (xf.w + xb.w) + og * uu.w;
        *(float4*)(y + (size_t)m * DD + bj + c4) = out;
    }
}

// ---------------------------------------------------------------------------
// kernel_launch: inputs 0:u 1:WA(dead) 2:WB 3:WAf(dead) 4:WBf 5:w1 6:w2 7:b 8:Wc
// Output: [y | gamma | final] flattened f32.
// ---------------------------------------------------------------------------
extern "C" void kernel_launch(void* const* d_in, const int* in_sizes, int n_in,
                              void* d_out, int out_size) {
    (void)in_sizes; (void)n_in; (void)out_size;
    const float* u   = (const float*)d_in[0];
    const float* WB  = (const float*)d_in[2];
    const float* WBf = (const float*)d_in[4];
    const float* w1  = (const float*)d_in[5];
    const float* w2  = (const float*)d_in[6];
    const float* b   = (const float*)d_in[7];
    const float* Wc  = (const float*)d_in[8];

    float* y         = (float*)d_out;
    float* gamma_out = y + Y_ELEMS;
    float* final_out = gamma_out + G_ELEMS;

    cudaFuncSetAttribute(gemm_fused_kernel,
                         cudaFuncAttributeMaxDynamicSharedMemorySize, SMEM_DYN);

    convert_w_kernel<<<(2 * DD * KK) / 1024, 256>>>(WB, WBf);
    precompute_vectors_kernel<<<DD / 256, 256>>>(WB, WBf, w1, w2, Wc);
    gamma_final_kernel<<<ROWS / 8, 256>>>(u, w1, w2, b, Wc, gamma_out, final_out);
    gemm_fused_kernel<<<dim3(DD / XN, ROWS / BM), 256, SMEM_DYN>>>(u, y);
}

// round 12
// speedup vs baseline: 6.2267x; 1.2000x over previous
#include <cuda_runtime.h>
#include <cuda_fp16.h>
#include <math.h>
#include <stdint.h>

// ---------------------------------------------------------------------------
// Problem: u (8,4096,1024) f32. Outputs: y (8,4096,1024), gamma, final.
// gamma kernel emits u in fp16; fused GEMM computes
//   C1[m] = u[m]   @ WB ^T (cols bj..bj+127)  (warps 0-7)
//   C2[m] = u[m+1] @ WBf^T (cols bj..bj+127)  (warps 8-15, +1 row shift)
// from ONE shared 129-row A tile, then writes y = g*(xf+xb)+(1-g)*u directly.
// 512 threads/CTA, 3-stage cp.async, one barrier per chunk.
// ---------------------------------------------------------------------------
#define BB 8
#define TT 4096
#define DD 1024
#define ROWS (BB * TT)              // 32768  (M)
#define KK   DD                     // 1024   (K)
#define Y_ELEMS   (ROWS * DD)
#define G_ELEMS   (ROWS)

// GEMM tiling
#define BM 128
#define XN 128                       // V-columns per CTA (each of C1, C2)
#define BK 64
#define STAGES 3
#define NCHUNK (KK / BK)             // 16
#define OFF_A 0                      // 129 rows x 128B
#define OFF_B 16640
#define STAGE_BYTES 49408            // A(16640) + B(32768)
#define SMEM_DYN (STAGES * STAGE_BYTES)   // 148224
#define CS_STRIDE 132                // fp32 staging stride (bank-friendly)

// Device-global scratch (no cudaMalloc anywhere)
__device__ __half g_Af[(size_t)ROWS * KK];       // 64 MiB  (u in fp16)
__device__ __half g_Bf[(size_t)2 * DD * KK];     // 4 MiB: rows 0..1023 WB, 1024.. WBf
__device__ float  g_vecs[4 * DD];                // a1 | a2 | cB | cBf
__device__ float  g_part[16][4][DD];             // precompute partials
__device__ float  g_gamma[ROWS];

// ---------------------------------------------------------------------------
// PTX helpers (sm_80-class only: cp.async, ldmatrix, mma.sync)
// ---------------------------------------------------------------------------
__device__ __forceinline__ uint32_t smem_u32(const void* p) {
    uint32_t a;
    asm("{ .reg .u64 t; cvta.to.shared.u64 t, %1; cvt.u32.u64 %0, t; }"
        : "=r"(a) : "l"(p));
    return a;
}
__device__ __forceinline__ void cpasync16(uint32_t dst, const void* src) {
    asm volatile("cp.async.cg.shared.global [%0], [%1], 16;" :: "r"(dst), "l"(src));
}
#define CP_COMMIT() asm volatile("cp.async.commit_group;" ::: "memory")
#define CP_WAIT_1() asm volatile("cp.async.wait_group 1;" ::: "memory")
#define CP_WAIT_0() asm volatile("cp.async.wait_group 0;" ::: "memory")

__device__ __forceinline__ void ldm_x4(uint32_t* r, uint32_t addr) {
    asm volatile("ldmatrix.sync.aligned.m8n8.x4.shared.b16 {%0,%1,%2,%3}, [%4];"
                 : "=r"(r[0]), "=r"(r[1]), "=r"(r[2]), "=r"(r[3]) : "r"(addr));
}
__device__ __forceinline__ void mma16816(float* c, const uint32_t* a,
                                         const uint32_t* b) {
    asm volatile("mma.sync.aligned.m16n8k16.row.col.f32.f16.f16.f32 "
                 "{%0,%1,%2,%3}, {%4,%5,%6,%7}, {%8,%9}, {%0,%1,%2,%3};"
                 : "+f"(c[0]), "+f"(c[1]), "+f"(c[2]), "+f"(c[3])
                 : "r"(a[0]), "r"(a[1]), "r"(a[2]), "r"(a[3]),
                   "r"(b[0]), "r"(b[1]));
}

// ---------------------------------------------------------------------------
// K0: [WB;WBf] -> fp16.
// ---------------------------------------------------------------------------
__global__ void convert_w_kernel(const float* __restrict__ WB,
                                 const float* __restrict__ WBf) {
    size_t i = ((size_t)blockIdx.x * 256 + threadIdx.x) * 4;
    const float* src = (i < (size_t)DD * DD) ? (WB + i) : (WBf + i - (size_t)DD * DD);
    float4 x = *(const float4*)src;
    union { __half h[4]; uint2 v; } H;
    H.h[0] = __float2half_rn(x.x);  H.h[1] = __float2half_rn(x.y);
    H.h[2] = __float2half_rn(x.z);  H.h[3] = __float2half_rn(x.w);
    *(uint2*)(g_Bf + i) = H.v;
}

// ---------------------------------------------------------------------------
// K1a/K1b: precompute a1 = w1@WB, a2 = w2@WBf, cB = Wc@WB, cBf = Wc@WBf.
// Two-phase, 64 CTAs, no atomics (deterministic): partials then reduce.
// ---------------------------------------------------------------------------
__global__ void precompute_partial_kernel(const float* __restrict__ WB,
                                          const float* __restrict__ WBf,
                                          const float* __restrict__ w1,
                                          const float* __restrict__ w2,
                                          const float* __restrict__ Wc) {
    int d  = blockIdx.x * 256 + threadIdx.x;   // 0..1023
    int e0 = blockIdx.y * 64;
    float a1 = 0.f, a2 = 0.f, cB = 0.f, cBf = 0.f;
#pragma unroll 8
    for (int e = e0; e < e0 + 64; ++e) {
        float wb = WB[e * DD + d];
        float wf = WBf[e * DD + d];
        a1  += w1[e] * wb;
        cB  += Wc[e] * wb;
        a2  += w2[e] * wf;
        cBf += Wc[e] * wf;
    }
    g_part[blockIdx.y][0][d] = a1;
    g_part[blockIdx.y][1][d] = a2;
    g_part[blockIdx.y][2][d] = cB;
    g_part[blockIdx.y][3][d] = cBf;
}

__global__ void precompute_reduce_kernel() {
    int d = blockIdx.x * 256 + threadIdx.x;    // 0..1023
#pragma unroll
    for (int v = 0; v < 4; ++v) {
        float s = 0.f;
#pragma unroll
        for (int k = 0; k < 16; ++k) s += g_part[k][v][d];
        g_vecs[v * DD + d] = s;
    }
}

// ---------------------------------------------------------------------------
// K2: gamma + final (fp32 exact dots) + emit u row in fp16 (feeds the GEMM).
// One warp per row.
// ---------------------------------------------------------------------------
__global__ void gamma_final_kernel(const float* __restrict__ u,
                                   const float* __restrict__ w1,
                                   const float* __restrict__ w2,
                                   const float* __restrict__ bias,
                                   const float* __restrict__ Wc,
                                   float* __restrict__ gamma_out,
                                   float* __restrict__ final_out) {
    int row  = blockIdx.x * 8 + (threadIdx.x >> 5);
    int lane = threadIdx.x & 31;
    int t = row & (TT - 1);

    const float* u1 = u + (size_t)row * DD;
    const float* u2 = (t == TT - 1) ? u1 : u1 + DD;
    const float* vS1 = (t == 0)      ? w1 : (g_vecs + 0);
    const float* vCf = (t == 0)      ? Wc : (g_vecs + 2 * DD);
    const float* vS2 = (t == TT - 1) ? w2 : (g_vecs + DD);
    const float* vCb = (t == TT - 1) ? Wc : (g_vecs + 3 * DD);

    float s1 = 0.f, s2 = 0.f, cf = 0.f, cb = 0.f, cu = 0.f;
#pragma unroll
    for (int it = 0; it < 8; ++it) {
        int i = lane * 4 + it * 128;
        float4 uu = *(const float4*)(u1 + i);
        float4 vv = *(const float4*)(u2 + i);
        float4 x1 = *(const float4*)(vS1 + i);
        float4 xc = *(const float4*)(vCf + i);
        float4 wc = *(const float4*)(Wc + i);
        float4 x2 = *(const float4*)(vS2 + i);
        float4 xb = *(const float4*)(vCb + i);
        union { __half h[4]; uint2 v; } H;
        H.h[0] = __float2half_rn(uu.x);  H.h[1] = __float2half_rn(uu.y);
        H.h[2] = __float2half_rn(uu.z);  H.h[3] = __float2half_rn(uu.w);
        *(uint2*)(g_Af + (size_t)row * DD + i) = H.v;

        s1 += uu.x * x1.x + uu.y * x1.y + uu.z * x1.z + uu.w * x1.w;
        cf += uu.x * xc.x + uu.y * xc.y + uu.z * xc.z + uu.w * xc.w;
        cu += uu.x * wc.x + uu.y * wc.y + uu.z * wc.z + uu.w * wc.w;
        s2 += vv.x * x2.x + vv.y * x2.y + vv.z * x2.z + vv.w * x2.w;
        cb += vv.x * xb.x + vv.y * xb.y + vv.z * xb.z + vv.w * xb.w;
    }
#pragma unroll
    for (int off = 16; off > 0; off >>= 1) {
        s1 += __shfl_down_sync(0xffffffffu, s1, off);
        s2 += __shfl_down_sync(0xffffffffu, s2, off);
        cf += __shfl_down_sync(0xffffffffu, cf, off);
        cb += __shfl_down_sync(0xffffffffu, cb, off);
        cu += __shfl_down_sync(0xffffffffu, cu, off);
    }
    if (lane == 0) {
        float g   = 1.f / (1.f + expf(-(s1 + s2 + bias[0])));
        float fin = 1.f / (1.f + expf(-(g * (cf + cb) + (1.f - g) * cu)));
        g_gamma[row]   = g;
        gamma_out[row] = g;
        final_out[row] = fin;
    }
}

// ---------------------------------------------------------------------------
// K3: fused HMMA GEMM + y epilogue. 512 threads (16 warps), 1 CTA/SM.
// Warps 0-7:  C1 (rows m),   B rows 0..127  (WB cols bj..bj+127)
// Warps 8-15: C2 (rows m+1), B rows 128..255 (WBf cols bj..bj+127)
// Per chunk:  wait -> sync -> issue loads for slot (c+2)%3 -> compute.
// grid (1024/128 = 8, 32768/128 = 256).
// ---------------------------------------------------------------------------
__global__ __launch_bounds__(512, 1)
void gemm_fused_kernel(const float* __restrict__ u, float* __restrict__ y) {
    extern __shared__ __align__(128) char dsm[];
    const uint32_t sbase = smem_u32(dsm);

    const int tid  = threadIdx.x;
    const int wid  = tid >> 5;
    const int lane = tid & 31;
    const int bm = blockIdx.y * BM;
    const int bj = blockIdx.x * XN;     // V column offset (0..896)

    const int grp = wid >> 3;           // 0: C1 (row m), 1: C2 (row m+1)
    const int w8  = wid & 7;
    const int wm  = (w8 >> 2) * 64;     // warp m offset (0/64)
    const int wn  = (w8 & 3) * 32;      // warp n offset within 128 (0/32/64/96)

    // -- global -> smem loader: 6 cp.async/thread + 1 extra row by 8 threads --
    const int lrow = tid >> 3;          // 0..63 (+j*64)
    const int lchk = tid & 7;
    auto load_stage = [&](int kchunk, int slot) {
        uint32_t sb = sbase + slot * STAGE_BYTES;
        int kb = kchunk * BK;
#pragma unroll
        for (int j = 0; j < 2; ++j) {   // A rows 0..127
            int r = lrow + j * 64;
            uint32_t so = (uint32_t)(r * 128) + (uint32_t)((lchk ^ (r & 7)) << 4);
            cpasync16(sb + OFF_A + so, g_Af + (size_t)(bm + r) * KK + kb + lchk * 8);
        }
#pragma unroll
        for (int j = 0; j < 4; ++j) {   // B rows 0..255 (0-127 WB, 128-255 WBf)
            int r = lrow + j * 64;
            uint32_t so = (uint32_t)(r * 128) + (uint32_t)((lchk ^ (r & 7)) << 4);
            int rb = bj + r + ((r >> 7) * (DD - XN));
            cpasync16(sb + OFF_B + so, g_Bf + (size_t)rb * KK + kb + lchk * 8);
        }
        if (tid < 8) {                  // A row 128 (clamped at last CTA)
            int ra = bm + 128;  if (ra > ROWS - 1) ra = ROWS - 1;
            cpasync16(sb + OFF_A + 128 * 128 + tid * 16,
                      g_Af + (size_t)ra * KK + kb + tid * 8);
        }
    };

    // -- per-thread ldmatrix bases (A row gets +grp shift) --
    uint32_t a_base[4], b_base[2];
    int a_rx[4], b_rx[2];
    const int a_ch = lane >> 4;
    const int b_ch = (lane >> 3) & 1;
#pragma unroll
    for (int mi = 0; mi < 4; ++mi) {
        int r = wm + mi * 16 + (lane & 15) + grp;
        a_base[mi] = OFF_A + (uint32_t)(r * 128);
        a_rx[mi] = r & 7;
    }
#pragma unroll
    for (int p = 0; p < 2; ++p) {
        int r = grp * 128 + wn + p * 16 + (lane & 7) + ((lane >> 4) << 3);
        b_base[p] = OFF_B + (uint32_t)(r * 128);
        b_rx[p] = r & 7;
    }

    float acc[4][4][4];
#pragma unroll
    for (int mi = 0; mi < 4; ++mi)
#pragma unroll
        for (int nj = 0; nj < 4; ++nj)
#pragma unroll
            for (int q = 0; q < 4; ++q) acc[mi][nj][q] = 0.f;

    load_stage(0, 0); CP_COMMIT();
    load_stage(1, 1); CP_COMMIT();

    for (int c = 0; c < NCHUNK; ++c) {
        if (c < NCHUNK - 1) CP_WAIT_1(); else CP_WAIT_0();
        __syncthreads();

        if (c + 2 < NCHUNK) {
            load_stage(c + 2, (c + 2) % STAGES);
            CP_COMMIT();
        }

        const uint32_t slot = sbase + (uint32_t)((c % STAGES) * STAGE_BYTES);

#pragma unroll
        for (int ks = 0; ks < 4; ++ks) {
            const int kc = ks * 2;
            uint32_t af[16], bf[8];
#pragma unroll
            for (int mi = 0; mi < 4; ++mi)
                ldm_x4(af + mi * 4, slot + a_base[mi] + (uint32_t)(((kc + a_ch) ^ a_rx[mi]) << 4));
#pragma unroll
            for (int p = 0; p < 2; ++p)
                ldm_x4(bf + p * 4, slot + b_base[p] + (uint32_t)(((kc + b_ch) ^ b_rx[p]) << 4));
#pragma unroll
            for (int mi = 0; mi < 4; ++mi)
#pragma unroll
                for (int nj = 0; nj < 4; ++nj)
                    mma16816(acc[mi][nj], af + mi * 4, bf + nj * 2);
        }
    }
    __syncthreads();   // all SMEM reads done before Cs staging reuses it

    // -- epilogue: stage C1/C2 (fp32) + gamma to smem, then write y --
    float* Cs = (float*)dsm;                       // [2][128][CS_STRIDE]
    float* Gs = Cs + 2 * 128 * CS_STRIDE;          // [128]
    const int lr = lane >> 2;
    const int lc = (lane & 3) * 2;
    float* Cg = Cs + (size_t)grp * 128 * CS_STRIDE;
#pragma unroll
    for (int mi = 0; mi < 4; ++mi) {
#pragma unroll
        for (int nj = 0; nj < 4; ++nj) {
            float* p0 = Cg + (size_t)(wm + mi * 16 + lr) * CS_STRIDE + wn + nj * 8 + lc;
            *(float2*)p0                    = make_float2(acc[mi][nj][0], acc[mi][nj][1]);
            *(float2*)(p0 + 8 * CS_STRIDE)  = make_float2(acc[mi][nj][2], acc[mi][nj][3]);
        }
    }
    if (tid < 128) Gs[tid] = g_gamma[bm + tid];
    __syncthreads();

#pragma unroll
    for (int it = 0; it < 8; ++it) {
        int idx = tid + it * 512;          // 0..4095  (128 rows x 32 col-quads)
        int row = idx >> 5;
        int c4  = (idx & 31) * 4;
        int m = bm + row;
        int t = m & (TT - 1);
        float g  = Gs[row];
        float og = 1.f - g;

        float4 uu = *(const float4*)(u + (size_t)m * DD + bj + c4);
        float4 c1 = *(const float4*)(Cs + (size_t)row * CS_STRIDE + c4);
        float4 c2 = *(const float4*)(Cs + (size_t)(128 + row) * CS_STRIDE + c4);
        float4 xf = (t == 0)      ? uu : c1;
        float4 xb = (t == TT - 1) ? uu : c2;

        float4 out;
        out.x = g * (xf.x + xb.x) + og * uu.x;
        out.y = g * (xf.y + xb.y) + og * uu.y;
        out.z = g * (xf.z + xb.z) + og * uu.z;
        out.w = g * (xf.w + xb.w) + og * uu.w;
        *(float4*)(y + (size_t)m * DD + bj + c4) = out;
    }
}

// ---------------------------------------------------------------------------
// kernel_launch: inputs 0:u 1:WA(dead) 2:WB 3:WAf(dead) 4:WBf 5:w1 6:w2 7:b 8:Wc
// Output: [y | gamma | final] flattened f32.
// ---------------------------------------------------------------------------
extern "C" void kernel_launch(void* const* d_in, const int* in_sizes, int n_in,
                              void* d_out, int out_size) {
    (void)in_sizes; (void)n_in; (void)out_size;
    const float* u   = (const float*)d_in[0];
    const float* WB  = (const float*)d_in[2];
    const float* WBf = (const float*)d_in[4];
    const float* w1  = (const float*)d_in[5];
    const float* w2  = (const float*)d_in[6];
    const float* b   = (const float*)d_in[7];
    const float* Wc  = (const float*)d_in[8];

    float* y         = (float*)d_out;
    float* gamma_out = y + Y_ELEMS;
    float* final_out = gamma_out + G_ELEMS;

    cudaFuncSetAttribute(gemm_fused_kernel,
                         cudaFuncAttributeMaxDynamicSharedMemorySize, SMEM_DYN);

    convert_w_kernel<<<(2 * DD * KK) / 1024, 256>>>(WB, WBf);
    precompute_partial_kernel<<<dim3(DD / 256, 16), 256>>>(WB, WBf, w1, w2, Wc);
    precompute_reduce_kernel<<<DD / 256, 256>>>();
    gamma_final_kernel<<<ROWS / 8, 256>>>(u, w1, w2, b, Wc, gamma_out, final_out);
    gemm_fused_kernel<<<dim3(DD / XN, ROWS / BM), 512, SMEM_DYN>>>(u, y);
}

// round 13
// speedup vs baseline: 6.8265x; 1.0963x over previous
#include <cuda_runtime.h>
#include <cuda_fp16.h>
#include <math.h>
#include <stdint.h>

// ---------------------------------------------------------------------------
// Problem: u (8,4096,1024) f32. Outputs: y (8,4096,1024), gamma, final.
// gamma kernel emits u in fp16; fused GEMM computes
//   C1[m] = u[m]   @ WB ^T (cols bj..bj+63)   (warps 0-3)
//   C2[m] = u[m+1] @ WBf^T (cols bj..bj+63)   (warps 4-7, +1 row shift)
// from ONE shared 129-row A tile, then writes y = g*(xf+xb)+(1-g)*u directly.
// 256 thr/CTA, 3-stage cp.async, one barrier per chunk, 2 CTAs/SM. (R11 shape)
// ---------------------------------------------------------------------------
#define BB 8
#define TT 4096
#define DD 1024
#define ROWS (BB * TT)              // 32768  (M)
#define KK   DD                     // 1024   (K)
#define Y_ELEMS   (ROWS * DD)
#define G_ELEMS   (ROWS)

// GEMM tiling
#define BM 128
#define XN 64                        // V-columns per CTA (each of C1, C2)
#define BK 64
#define STAGES 3
#define NCHUNK (KK / BK)             // 16
#define OFF_A 0                      // 129 rows x 128B
#define OFF_B 16640
#define STAGE_BYTES 33024            // A(16640) + B(16384)
#define SMEM_DYN (STAGES * STAGE_BYTES)   // 99072
#define CS_STRIDE 68                 // fp32 staging stride (bank-friendly)

// Device-global scratch (no cudaMalloc anywhere)
__device__ __half g_Af[(size_t)ROWS * KK];       // 64 MiB  (u in fp16)
__device__ __half g_Bf[(size_t)2 * DD * KK];     // 4 MiB: rows 0..1023 WB, 1024.. WBf
__device__ float  g_vecs[4 * DD];                // a1 | a2 | cB | cBf
__device__ float  g_part[16][4][DD];             // precompute partials
__device__ float  g_gamma[ROWS];

// ---------------------------------------------------------------------------
// PTX helpers (sm_80-class only: cp.async, ldmatrix, mma.sync)
// ---------------------------------------------------------------------------
__device__ __forceinline__ uint32_t smem_u32(const void* p) {
    uint32_t a;
    asm("{ .reg .u64 t; cvta.to.shared.u64 t, %1; cvt.u32.u64 %0, t; }"
        : "=r"(a) : "l"(p));
    return a;
}
__device__ __forceinline__ void cpasync16(uint32_t dst, const void* src) {
    asm volatile("cp.async.cg.shared.global [%0], [%1], 16;" :: "r"(dst), "l"(src));
}
#define CP_COMMIT() asm volatile("cp.async.commit_group;" ::: "memory")
#define CP_WAIT_1() asm volatile("cp.async.wait_group 1;" ::: "memory")
#define CP_WAIT_0() asm volatile("cp.async.wait_group 0;" ::: "memory")

__device__ __forceinline__ void ldm_x4(uint32_t* r, uint32_t addr) {
    asm volatile("ldmatrix.sync.aligned.m8n8.x4.shared.b16 {%0,%1,%2,%3}, [%4];"
                 : "=r"(r[0]), "=r"(r[1]), "=r"(r[2]), "=r"(r[3]) : "r"(addr));
}
__device__ __forceinline__ void mma16816(float* c, const uint32_t* a,
                                         const uint32_t* b) {
    asm volatile("mma.sync.aligned.m16n8k16.row.col.f32.f16.f16.f32 "
                 "{%0,%1,%2,%3}, {%4,%5,%6,%7}, {%8,%9}, {%0,%1,%2,%3};"
                 : "+f"(c[0]), "+f"(c[1]), "+f"(c[2]), "+f"(c[3])
                 : "r"(a[0]), "r"(a[1]), "r"(a[2]), "r"(a[3]),
                   "r"(b[0]), "r"(b[1]));
}

// ---------------------------------------------------------------------------
// K0: [WB;WBf] -> fp16.
// ---------------------------------------------------------------------------
__global__ void convert_w_kernel(const float* __restrict__ WB,
                                 const float* __restrict__ WBf) {
    size_t i = ((size_t)blockIdx.x * 256 + threadIdx.x) * 4;
    const float* src = (i < (size_t)DD * DD) ? (WB + i) : (WBf + i - (size_t)DD * DD);
    float4 x = *(const float4*)src;
    union { __half h[4]; uint2 v; } H;
    H.h[0] = __float2half_rn(x.x);  H.h[1] = __float2half_rn(x.y);
    H.h[2] = __float2half_rn(x.z);  H.h[3] = __float2half_rn(x.w);
    *(uint2*)(g_Bf + i) = H.v;
}

// ---------------------------------------------------------------------------
// K1a/K1b: precompute a1 = w1@WB, a2 = w2@WBf, cB = Wc@WB, cBf = Wc@WBf.
// Two-phase, 64 CTAs, no atomics (deterministic): partials then reduce.
// ---------------------------------------------------------------------------
__global__ void precompute_partial_kernel(const float* __restrict__ WB,
                                          const float* __restrict__ WBf,
                                          const float* __restrict__ w1,
                                          const float* __restrict__ w2,
                                          const float* __restrict__ Wc) {
    int d  = blockIdx.x * 256 + threadIdx.x;   // 0..1023
    int e0 = blockIdx.y * 64;
    float a1 = 0.f, a2 = 0.f, cB = 0.f, cBf = 0.f;
#pragma unroll 8
    for (int e = e0; e < e0 + 64; ++e) {
        float wb = WB[e * DD + d];
        float wf = WBf[e * DD + d];
        a1  += w1[e] * wb;
        cB  += Wc[e] * wb;
        a2  += w2[e] * wf;
        cBf += Wc[e] * wf;
    }
    g_part[blockIdx.y][0][d] = a1;
    g_part[blockIdx.y][1][d] = a2;
    g_part[blockIdx.y][2][d] = cB;
    g_part[blockIdx.y][3][d] = cBf;
}

__global__ void precompute_reduce_kernel() {
    int d = blockIdx.x * 256 + threadIdx.x;    // 0..1023
#pragma unroll
    for (int v = 0; v < 4; ++v) {
        float s = 0.f;
#pragma unroll
        for (int k = 0; k < 16; ++k) s += g_part[k][v][d];
        g_vecs[v * DD + d] = s;
    }
}

// ---------------------------------------------------------------------------
// K2: gamma + final (fp32 exact dots) + emit u row in fp16 (feeds the GEMM).
// One warp per row. Reg-capped for 40 warps/SM (latency-bound streamer).
// ---------------------------------------------------------------------------
__global__ __launch_bounds__(256, 5)
void gamma_final_kernel(const float* __restrict__ u,
                        const float* __restrict__ w1,
                        const float* __restrict__ w2,
                        const float* __restrict__ bias,
                        const float* __restrict__ Wc,
                        float* __restrict__ gamma_out,
                        float* __restrict__ final_out) {
    int row  = blockIdx.x * 8 + (threadIdx.x >> 5);
    int lane = threadIdx.x & 31;
    int t = row & (TT - 1);

    const float* u1 = u + (size_t)row * DD;
    const float* u2 = (t == TT - 1) ? u1 : u1 + DD;
    const float* vS1 = (t == 0)      ? w1 : (g_vecs + 0);
    const float* vCf = (t == 0)      ? Wc : (g_vecs + 2 * DD);
    const float* vS2 = (t == TT - 1) ? w2 : (g_vecs + DD);
    const float* vCb = (t == TT - 1) ? Wc : (g_vecs + 3 * DD);

    float s1 = 0.f, s2 = 0.f, cf = 0.f, cb = 0.f, cu = 0.f;
#pragma unroll
    for (int it = 0; it < 8; ++it) {
        int i = lane * 4 + it * 128;
        float4 uu = *(const float4*)(u1 + i);
        float4 vv = *(const float4*)(u2 + i);
        float4 x1 = *(const float4*)(vS1 + i);
        float4 xc = *(const float4*)(vCf + i);
        float4 wc = *(const float4*)(Wc + i);
        float4 x2 = *(const float4*)(vS2 + i);
        float4 xb = *(const float4*)(vCb + i);
        union { __half h[4]; uint2 v; } H;
        H.h[0] = __float2half_rn(uu.x);  H.h[1] = __float2half_rn(uu.y);
        H.h[2] = __float2half_rn(uu.z);  H.h[3] = __float2half_rn(uu.w);
        *(uint2*)(g_Af + (size_t)row * DD + i) = H.v;

        s1 += uu.x * x1.x + uu.y * x1.y + uu.z * x1.z + uu.w * x1.w;
        cf += uu.x * xc.x + uu.y * xc.y + uu.z * xc.z + uu.w * xc.w;
        cu += uu.x * wc.x + uu.y * wc.y + uu.z * wc.z + uu.w * wc.w;
        s2 += vv.x * x2.x + vv.y * x2.y + vv.z * x2.z + vv.w * x2.w;
        cb += vv.x * xb.x + vv.y * xb.y + vv.z * xb.z + vv.w * xb.w;
    }
#pragma unroll
    for (int off = 16; off > 0; off >>= 1) {
        s1 += __shfl_down_sync(0xffffffffu, s1, off);
        s2 += __shfl_down_sync(0xffffffffu, s2, off);
        cf += __shfl_down_sync(0xffffffffu, cf, off);
        cb += __shfl_down_sync(0xffffffffu, cb, off);
        cu += __shfl_down_sync(0xffffffffu, cu, off);
    }
    if (lane == 0) {
        float g   = 1.f / (1.f + expf(-(s1 + s2 + bias[0])));
        float fin = 1.f / (1.f + expf(-(g * (cf + cb) + (1.f - g) * cu)));
        g_gamma[row]   = g;
        gamma_out[row] = g;
        final_out[row] = fin;
    }
}

// ---------------------------------------------------------------------------
// K3: fused HMMA GEMM + y epilogue. 256 threads, 2 CTAs/SM, ONE barrier/chunk.
// Per chunk c:  wait(g_c) -> sync -> issue loads for slot (c+2)%3 -> compute.
// grid (1024/64 = 16, 32768/128 = 256).
// ---------------------------------------------------------------------------
__global__ __launch_bounds__(256, 2)
void gemm_fused_kernel(const float* __restrict__ u, float* __restrict__ y) {
    extern __shared__ __align__(128) char dsm[];
    const uint32_t sbase = smem_u32(dsm);

    const int tid  = threadIdx.x;
    const int wid  = tid >> 5;
    const int lane = tid & 31;
    const int bm = blockIdx.y * BM;
    const int bj = blockIdx.x * XN;     // V column offset (0..960)

    const int grp = wid >> 2;           // 0: C1 (row m), 1: C2 (row m+1)
    const int w2  = wid & 3;
    const int wm  = (w2 >> 1) * 64;     // warp m offset (0/64)
    const int wn  = (w2 & 1) * 32;      // warp n offset within 64 (0/32)

    // -- global -> smem loader: 8 cp.async/thread + 1 extra row by 8 threads --
    const int lrow = tid >> 3;          // 0..31 (+j*32)
    const int lchk = tid & 7;
    auto load_stage = [&](int kchunk, int slot) {
        uint32_t sb = sbase + slot * STAGE_BYTES;
        int kb = kchunk * BK;
#pragma unroll
        for (int j = 0; j < 4; ++j) {
            int r = lrow + j * 32;
            uint32_t so = (uint32_t)(r * 128) + (uint32_t)((lchk ^ (r & 7)) << 4);
            int rb = bj + r + ((r >> 6) * (DD - XN));   // rows 0-63: WB, 64-127: WBf
            cpasync16(sb + OFF_A + so, g_Af + (size_t)(bm + r) * KK + kb + lchk * 8);
            cpasync16(sb + OFF_B + so, g_Bf + (size_t)rb * KK + kb + lchk * 8);
        }
        if (tid < 8) {                  // A row 128 (clamped at last CTA)
            int ra = bm + 128;  if (ra > ROWS - 1) ra = ROWS - 1;
            cpasync16(sb + OFF_A + 128 * 128 + tid * 16,
                      g_Af + (size_t)ra * KK + kb + tid * 8);
        }
    };

    // -- per-thread ldmatrix bases (A row gets +grp shift) --
    uint32_t a_base[4], b_base[2];
    int a_rx[4], b_rx[2];
    const int a_ch = lane >> 4;
    const int b_ch = (lane >> 3) & 1;
#pragma unroll
    for (int mi = 0; mi < 4; ++mi) {
        int r = wm + mi * 16 + (lane & 15) + grp;
        a_base[mi] = OFF_A + (uint32_t)(r * 128);
        a_rx[mi] = r & 7;
    }
#pragma unroll
    for (int p = 0; p < 2; ++p) {
        int r = grp * 64 + wn + p * 16 + (lane & 7) + ((lane >> 4) << 3);
        b_base[p] = OFF_B + (uint32_t)(r * 128);
        b_rx[p] = r & 7;
    }

    float acc[4][4][4];
#pragma unroll
    for (int mi = 0; mi < 4; ++mi)
#pragma unroll
        for (int nj = 0; nj < 4; ++nj)
#pragma unroll
            for (int q = 0; q < 4; ++q) acc[mi][nj][q] = 0.f;

    load_stage(0, 0); CP_COMMIT();
    load_stage(1, 1); CP_COMMIT();

    for (int c = 0; c < NCHUNK; ++c) {
        if (c < NCHUNK - 1) CP_WAIT_1(); else CP_WAIT_0();
        __syncthreads();

        if (c + 2 < NCHUNK) {
            load_stage(c + 2, (c + 2) % STAGES);
            CP_COMMIT();
        }

        const uint32_t slot = sbase + (uint32_t)((c % STAGES) * STAGE_BYTES);

#pragma unroll
        for (int ks = 0; ks < 4; ++ks) {
            const int kc = ks * 2;
            uint32_t af[16], bf[8];
#pragma unroll
            for (int mi = 0; mi < 4; ++mi)
                ldm_x4(af + mi * 4, slot + a_base[mi] + (uint32_t)(((kc + a_ch) ^ a_rx[mi]) << 4));
#pragma unroll
            for (int p = 0; p < 2; ++p)
                ldm_x4(bf + p * 4, slot + b_base[p] + (uint32_t)(((kc + b_ch) ^ b_rx[p]) << 4));
#pragma unroll
            for (int mi = 0; mi < 4; ++mi)
#pragma unroll
                for (int nj = 0; nj < 4; ++nj)
                    mma16816(acc[mi][nj], af + mi * 4, bf + nj * 2);
        }
    }
    __syncthreads();   // everyone done reading SMEM before Cs staging reuses it

    // -- epilogue: stage C1/C2 (fp32) + gamma to smem, then write y --
    float* Cs = (float*)dsm;                       // [2][128][CS_STRIDE]
    float* Gs = Cs + 2 * 128 * CS_STRIDE;          // [128]
    const int lr = lane >> 2;
    const int lc = (lane & 3) * 2;
    float* Cg = Cs + (size_t)grp * 128 * CS_STRIDE;
#pragma unroll
    for (int mi = 0; mi < 4; ++mi) {
#pragma unroll
        for (int nj = 0; nj < 4; ++nj) {
            float* p0 = Cg + (size_t)(wm + mi * 16 + lr) * CS_STRIDE + wn + nj * 8 + lc;
            *(float2*)p0                    = make_float2(acc[mi][nj][0], acc[mi][nj][1]);
            *(float2*)(p0 + 8 * CS_STRIDE)  = make_float2(acc[mi][nj][2], acc[mi][nj][3]);
        }
    }
    if (tid < 128) Gs[tid] = g_gamma[bm + tid];
    __syncthreads();

#pragma unroll
    for (int it = 0; it < 8; ++it) {
        int idx = tid + it * 256;          // 0..2047  (128 rows x 16 col-quads)
        int row = idx >> 4;
        int c4  = (idx & 15) * 4;
        int m = bm + row;
        int t = m & (TT - 1);
        float g  = Gs[row];
        float og = 1.f - g;

        float4 uu = *(const float4*)(u + (size_t)m * DD + bj + c4);
        float4 c1 = *(const float4*)(Cs + (size_t)row * CS_STRIDE + c4);
        float4 c2 = *(const float4*)(Cs + (size_t)(128 + row) * CS_STRIDE + c4);
        float4 xf = (t == 0)      ? uu : c1;
        float4 xb = (t == TT - 1) ? uu : c2;

        float4 out;
        out.x = g * (xf.x + xb.x) + og * uu.x;
        out.y = g * (xf.y + xb.y) + og * uu.y;
        out.z = g * (xf.z + xb.z) + og * uu.z;
        out.w = g * (xf.w + xb.w) + og * uu.w;
        *(float4*)(y + (size_t)m * DD + bj + c4) = out;
    }
}

// ---------------------------------------------------------------------------
// kernel_launch: inputs 0:u 1:WA(dead) 2:WB 3:WAf(dead) 4:WBf 5:w1 6:w2 7:b 8:Wc
// Output: [y | gamma | final] flattened f32.
// ---------------------------------------------------------------------------
extern "C" void kernel_launch(void* const* d_in, const int* in_sizes, int n_in,
                              void* d_out, int out_size) {
    (void)in_sizes; (void)n_in; (void)out_size;
    const float* u   = (const float*)d_in[0];
    const float* WB  = (const float*)d_in[2];
    const float* WBf = (const float*)d_in[4];
    const float* w1  = (const float*)d_in[5];
    const float* w2  = (const float*)d_in[6];
    const float* b   = (const float*)d_in[7];
    const float* Wc  = (const float*)d_in[8];

    float* y         = (float*)d_out;
    float* gamma_out = y + Y_ELEMS;
    float* final_out = gamma_out + G_ELEMS;

    cudaFuncSetAttribute(gemm_fused_kernel,
                         cudaFuncAttributeMaxDynamicSharedMemorySize, SMEM_DYN);

    convert_w_kernel<<<(2 * DD * KK) / 1024, 256>>>(WB, WBf);
    precompute_partial_kernel<<<dim3(DD / 256, 16), 256>>>(WB, WBf, w1, w2, Wc);
    precompute_reduce_kernel<<<DD / 256, 256>>>();
    gamma_final_kernel<<<ROWS / 8, 256>>>(u, w1, w2, b, Wc, gamma_out, final_out);
    gemm_fused_kernel<<<dim3(DD / XN, ROWS / BM), 256, SMEM_DYN>>>(u, y);
}